// round 5
// baseline (speedup 1.0000x reference)
#include <cuda_runtime.h>
#include <math.h>

#define NB   4
#define NCLS 3
#define FH   256       // feature H=W
#define CH   128       // coarse H=W
#define NIN  128
#define KIN  131
#define FCK  132       // KIN padded to 11*12
#define KCH  12
#define NCH  11
#define PPB  8192
#define PTOT 32768
#define KEYSTRIDE 262144
#define TOPK 8192u
#define XS_STRIDE 132
#define WCHUNK 1536    // float2 per chunk (12*128)

// ---------------- scratch ----------------
__device__ float        g_featT[(size_t)NB*FH*FH*NIN];   // NHWC features
__device__ float        g_sem256[NB*NCLS*256*256];
__device__ unsigned int g_keys[NB*KEYSTRIDE];
__device__ unsigned int g_hist2[NB*4096];
__device__ unsigned long long g_cand[(size_t)NB*KEYSTRIDE];
__device__ int          g_bstar[NB];
__device__ int          g_kRem[NB];
__device__ int          g_selCount[NB];
__device__ int          g_candCount[NB];
__device__ int          g_done1[NB];
__device__ int          g_done2[NB];
__device__ int          g_idx[PTOT];
__device__ float2       g_Wd[(size_t)3*FCK*NIN];         // dup-packed weights, chunk-contiguous

__device__ __forceinline__ unsigned int fkey(float f) {
    unsigned int u = __float_as_uint(f);
    return (u & 0x80000000u) ? ~u : (u | 0x80000000u);
}
__device__ __forceinline__ unsigned long long ffma2(unsigned long long a, unsigned long long b, unsigned long long c) {
    unsigned long long d;
    asm("fma.rn.f32x2 %0, %1, %2, %3;" : "=l"(d) : "l"(a), "l"(b), "l"(c));
    return d;
}
__device__ __forceinline__ void unpack2(unsigned long long v, float& lo, float& hi) {
    unsigned int a, b;
    asm("mov.b64 {%0,%1}, %2;" : "=r"(a), "=r"(b) : "l"(v));
    lo = __uint_as_float(a); hi = __uint_as_float(b);
}

// ---------------- one-time prep: histograms, counters, weight pack ----------------
__global__ void prep_kernel(const float* __restrict__ w1, const float* __restrict__ w2,
                            const float* __restrict__ w3) {
    int i = blockIdx.x*blockDim.x + threadIdx.x;
    int stride = gridDim.x*blockDim.x;
    for (int j = i; j < NB*4096; j += stride) g_hist2[j] = 0;
    if (i < NB) { g_done1[i] = 0; g_done2[i] = 0; g_selCount[i] = 0; g_candCount[i] = 0; }
    for (int j = i; j < 3*FCK*NIN; j += stride) {
        int l = j / (FCK*NIN); int r = j - l*(FCK*NIN);
        int k = r >> 7; int o = r & 127;
        const float* w = (l == 0) ? w1 : ((l == 1) ? w2 : w3);
        float v = (k < KIN) ? w[o*KIN + k] : 0.f;
        g_Wd[j] = make_float2(v, v);
    }
}

// ---------------- features NCHW -> NHWC (side stream) ----------------
__global__ void transpose_kernel(const float* __restrict__ f) {
    __shared__ float tile[32][33];
    int n = blockIdx.z;
    int pix0 = blockIdx.x * 32;
    int c0   = blockIdx.y * 32;
    int tx = threadIdx.x, ty = threadIdx.y;
    #pragma unroll
    for (int i = ty; i < 32; i += 8)
        tile[i][tx] = f[(size_t)(n*NIN + c0 + i)*(FH*FH) + pix0 + tx];
    __syncthreads();
    #pragma unroll
    for (int i = ty; i < 32; i += 8)
        g_featT[(size_t)(n*(FH*FH) + pix0 + i)*NIN + c0 + tx] = tile[tx][i];
}

// ---------------- K1: upsample + keys + hist; last block per batch resolves threshold ----------------
__global__ void upsample_sel(const float* __restrict__ in, float* __restrict__ out, int logW) {
    __shared__ unsigned int sh[4096];
    __shared__ unsigned int wsum[8];
    __shared__ int sh_last;
    int n = blockIdx.y;
    int t = threadIdx.x;                    // 256
    for (int i = t; i < 4096; i += 256) sh[i] = 0;
    __syncthreads();
    int W = 1 << logW, Hin = W >> 1;
    int HW = W << logW;
    for (int pix = blockIdx.x*256 + t; pix < HW; pix += gridDim.x*256) {
        int y = pix >> logW;  int x = pix & (W - 1);
        int y0 = (y - 1) >> 1, x0 = (x - 1) >> 1;
        float wy1 = (y & 1) ? 0.25f : 0.75f;
        float wx1 = (x & 1) ? 0.25f : 0.75f;
        int y1 = y0 + 1, x1 = x0 + 1;
        int xa = (x0 < 0) ? 0 : x0;
        int xb = (x1 > Hin-1) ? Hin-1 : x1;
        float v[NCLS];
        #pragma unroll
        for (int c = 0; c < NCLS; c++) {
            const float* p = in + (size_t)(n*NCLS + c)*Hin*Hin;
            float colA, colB;
            if (y0 < 0)            { colA = p[xa];               colB = p[xb]; }
            else if (y1 > Hin - 1) { colA = p[(Hin-1)*Hin + xa]; colB = p[(Hin-1)*Hin + xb]; }
            else {
                colA = (1.f - wy1)*p[y0*Hin + xa] + wy1*p[y1*Hin + xa];
                colB = (1.f - wy1)*p[y0*Hin + xb] + wy1*p[y1*Hin + xb];
            }
            float vv;
            if (x0 < 0)            vv = colA;
            else if (x1 > Hin - 1) vv = colB;
            else                   vv = (1.f - wx1)*colA + wx1*colB;
            v[c] = vv;
            out[(size_t)(n*NCLS + c)*HW + pix] = vv;
        }
        float hi = fmaxf(v[0], v[1]), lo = fminf(v[0], v[1]);
        float m1 = fmaxf(hi, v[2]);
        float m2 = fmaxf(lo, fminf(hi, v[2]));
        unsigned int key = fkey(m2 - m1);
        g_keys[n*KEYSTRIDE + pix] = key;
        atomicAdd(&sh[key >> 20], 1u);
    }
    __syncthreads();
    for (int i = t; i < 4096; i += 256) {
        unsigned int v = sh[i];
        if (v) atomicAdd(&g_hist2[n*4096 + i], v);
    }
    // ---- last block per batch resolves ----
    __threadfence();
    if (t == 0) {
        int old = atomicAdd(&g_done1[n], 1);
        sh_last = (old == (int)gridDim.x - 1);
    }
    __syncthreads();
    if (!sh_last) return;
    unsigned int* gh = g_hist2 + n*4096;
    int lane = t & 31, wrp = t >> 5;
    int base = 4095 - (t << 4);
    unsigned int h[16];
    unsigned int sum = 0;
    #pragma unroll
    for (int j = 0; j < 16; j++) { h[j] = gh[base - j]; sum += h[j]; }
    unsigned int v = sum;
    #pragma unroll
    for (int off = 1; off < 32; off <<= 1) {
        unsigned int u = __shfl_up_sync(0xffffffffu, v, off);
        if (lane >= off) v += u;
    }
    if (lane == 31) wsum[wrp] = v;
    __syncthreads();
    if (wrp == 0 && lane < 8) {
        unsigned int w = wsum[lane];
        #pragma unroll
        for (int off = 1; off < 8; off <<= 1) {
            unsigned int u = __shfl_up_sync(0xffu, w, off);
            if (lane >= off) w += u;
        }
        wsum[lane] = w;
    }
    __syncthreads();
    unsigned int incl = v + (wrp ? wsum[wrp-1] : 0u);
    unsigned int excl = incl - sum;
    if (excl < TOPK && TOPK <= incl) {
        unsigned int c = excl;
        #pragma unroll
        for (int j = 0; j < 16; j++) {
            if (c + h[j] >= TOPK) { g_bstar[n] = base - j; g_kRem[n] = (int)(TOPK - c); break; }
            c += h[j];
        }
    }
    #pragma unroll
    for (int j = 0; j < 16; j++) gh[base - j] = 0;       // clean for next step
    if (t == 0) { g_selCount[n] = 0; g_candCount[n] = 0; g_done1[n] = 0; }
}

// ---------------- K2: compact; last block per batch runs exact candidate radix select ----------------
__global__ void __launch_bounds__(1024)
compact_sel(int HW) {
    __shared__ unsigned int hist[1024];
    __shared__ unsigned int wsum[32];
    __shared__ int sh_d, sh_last;
    __shared__ unsigned int sh_sub;
    int n = blockIdx.y;
    int t = threadIdx.x;                    // 1024
    int lane = t & 31, wrp = t >> 5;
    int bstar = g_bstar[n];
    const unsigned int* keys = g_keys + n*KEYSTRIDE;
    unsigned long long* cand = g_cand + (size_t)n*KEYSTRIDE;
    for (int i = blockIdx.x*1024 + t; i < HW; i += gridDim.x*1024) {
        unsigned int key = keys[i];
        int b = (int)(key >> 20);
        if (b > bstar) {
            int p = atomicAdd(&g_selCount[n], 1);
            g_idx[n*PPB + p] = i;
        } else if (b == bstar) {
            int p = atomicAdd(&g_candCount[n], 1);
            cand[p] = (((unsigned long long)(key & 0xFFFFFu)) << 18) | (unsigned int)((~i) & 0x3FFFF);
        }
    }
    __threadfence();
    if (t == 0) {
        int old = atomicAdd(&g_done2[n], 1);
        sh_last = (old == (int)gridDim.x - 1);
    }
    __syncthreads();
    if (!sh_last) return;
    // ---- candidate select (this block only) ----
    int m = g_candCount[n];
    unsigned int need = (unsigned int)g_kRem[n];
    unsigned long long prefix = 0, pmask = 0;
    if (m > (int)need) {
        #pragma unroll
        for (int pass = 0; pass < 4; pass++) {
            int shift = 30 - 10*pass;
            hist[t] = 0;
            __syncthreads();
            for (int i = t; i < m; i += 1024) {
                unsigned long long c = cand[i];
                if ((c & pmask) == prefix)
                    atomicAdd(&hist[(unsigned int)(c >> shift) & 1023u], 1u);
            }
            __syncthreads();
            unsigned int val = hist[1023 - t];
            unsigned int v = val;
            #pragma unroll
            for (int off = 1; off < 32; off <<= 1) {
                unsigned int u = __shfl_up_sync(0xffffffffu, v, off);
                if (lane >= off) v += u;
            }
            if (lane == 31) wsum[wrp] = v;
            __syncthreads();
            if (wrp == 0) {
                unsigned int w = wsum[lane];
                #pragma unroll
                for (int off = 1; off < 32; off <<= 1) {
                    unsigned int u = __shfl_up_sync(0xffffffffu, w, off);
                    if (lane >= off) w += u;
                }
                wsum[lane] = w;
            }
            __syncthreads();
            unsigned int incl = v + (wrp ? wsum[wrp-1] : 0u);
            unsigned int excl = incl - val;
            if (excl < need && need <= incl) { sh_d = 1023 - t; sh_sub = excl; }
            __syncthreads();
            need -= sh_sub;
            prefix |= ((unsigned long long)(unsigned int)sh_d) << shift;
            pmask  |= 1023ull << shift;
            __syncthreads();
        }
    }
    for (int i = t; i < m; i += 1024) {
        unsigned long long c = cand[i];
        if (c >= prefix) {
            int p = atomicAdd(&g_selCount[n], 1);
            g_idx[n*PPB + p] = (int)((~c) & 0x3FFFF);
        }
    }
    if (t == 0) g_done2[n] = 0;
}

// ---------------- mega MLP: gather + 3 FC layers + head + scatter ----------------
__global__ void __launch_bounds__(256, 2)
mlp_kernel(const float* __restrict__ coarse, const float2* __restrict__ Wd,
           const float* __restrict__ b1, const float* __restrict__ b2, const float* __restrict__ b3,
           const float* __restrict__ wph, const float* __restrict__ bph,
           float* __restrict__ sem, int HW, int logW) {
    extern __shared__ float sm[];
    float* Xs  = sm;                      // [132][132]
    float* Wsm = sm + FCK*XS_STRIDE;      // 2*1536 float2 (also gather tile scratch)
    __shared__ int   sx0[128], sy0[128];
    __shared__ float sw0[128], sw1[128], sw2[128], sw3[128], spx[128], spy[128];

    int tid = threadIdx.x, lane = tid & 31, wrp = tid >> 5;
    int pBase = blockIdx.x * 128;
    int n = pBase >> 13;

    if (tid < 128) {
        int id = g_idx[pBase + tid];
        int W = 1 << logW;
        float inv = 1.f / (float)W;
        float px = ((float)(id & (W-1)) + 0.5f) * inv;
        float py = ((float)(id >> logW) + 0.5f) * inv;
        spx[tid] = px; spy[tid] = py;
        float fx = px * 256.f - 0.5f, fy = py * 256.f - 0.5f;
        float fx0 = floorf(fx), fy0 = floorf(fy);
        float wx1 = fx - fx0, wy1 = fy - fy0;
        sx0[tid] = (int)fx0; sy0[tid] = (int)fy0;
        sw0[tid] = (1.f-wx1)*(1.f-wy1);
        sw1[tid] = wx1*(1.f-wy1);
        sw2[tid] = (1.f-wx1)*wy1;
        sw3[tid] = wx1*wy1;
    }
    __syncthreads();

    const float* fbase = g_featT + (size_t)n*FH*FH*NIN;
    float* tile = Wsm;                    // [132][33]
    int off = lane << 2;
    for (int s = 0; s < 4; s++) {
        #pragma unroll
        for (int it = 0; it < 4; it++) {
            int j = wrp + it*8;
            int jg = s*32 + j;
            int x0 = sx0[jg], y0 = sy0[jg];
            bool xv0 = (x0 >= 0), xv1 = (x0+1 < FH), yv0 = (y0 >= 0), yv1 = (y0+1 < FH);
            float a0 = 0.f, a1 = 0.f, a2 = 0.f, a3 = 0.f;
            if (xv0 && yv0) { float w = sw0[jg]; float4 v = *(const float4*)(fbase + (size_t)((y0  )*FH + x0  )*NIN + off);
                              a0 += w*v.x; a1 += w*v.y; a2 += w*v.z; a3 += w*v.w; }
            if (xv1 && yv0) { float w = sw1[jg]; float4 v = *(const float4*)(fbase + (size_t)((y0  )*FH + x0+1)*NIN + off);
                              a0 += w*v.x; a1 += w*v.y; a2 += w*v.z; a3 += w*v.w; }
            if (xv0 && yv1) { float w = sw2[jg]; float4 v = *(const float4*)(fbase + (size_t)((y0+1)*FH + x0  )*NIN + off);
                              a0 += w*v.x; a1 += w*v.y; a2 += w*v.z; a3 += w*v.w; }
            if (xv1 && yv1) { float w = sw3[jg]; float4 v = *(const float4*)(fbase + (size_t)((y0+1)*FH + x0+1)*NIN + off);
                              a0 += w*v.x; a1 += w*v.y; a2 += w*v.z; a3 += w*v.w; }
            tile[(off+0)*33 + j] = a0; tile[(off+1)*33 + j] = a1;
            tile[(off+2)*33 + j] = a2; tile[(off+3)*33 + j] = a3;
        }
        if (tid < 96) {
            int j = tid / 3, cc = tid - (tid/3)*3;
            int jg = s*32 + j;
            float cx = spx[jg]*128.f - 0.5f, cy = spy[jg]*128.f - 0.5f;
            float cx0f = floorf(cx), cy0f = floorf(cy);
            int x0 = (int)cx0f, y0 = (int)cy0f;
            float wx1 = cx - cx0f, wy1 = cy - cy0f;
            const float* p = coarse + (size_t)(n*NCLS + cc)*CH*CH;
            float acc = 0.f;
            if (x0 >= 0   && y0 >= 0  ) acc += (1.f-wx1)*(1.f-wy1)*p[y0*CH + x0];
            if (x0+1 < CH && y0 >= 0  ) acc += wx1*(1.f-wy1)*p[y0*CH + x0+1];
            if (x0 >= 0   && y0+1 < CH) acc += (1.f-wx1)*wy1*p[(y0+1)*CH + x0];
            if (x0+1 < CH && y0+1 < CH) acc += wx1*wy1*p[(y0+1)*CH + x0+1];
            tile[(NIN+cc)*33 + j] = acc;
        }
        __syncthreads();
        for (int idx = tid; idx < 132*32; idx += 256) {
            int r = idx >> 5, j = idx & 31;
            float v = (r < KIN) ? tile[r*33 + j] : 0.f;
            Xs[r*XS_STRIDE + s*32 + j] = v;
        }
        __syncthreads();
    }

    {
        const float4* wg = (const float4*)Wd;
        float4* wd = (float4*)Wsm;
        wd[tid] = wg[tid]; wd[tid+256] = wg[tid+256]; wd[tid+512] = wg[tid+512];
    }
    __syncthreads();

    int o0 = (tid >> 4) << 3;
    int p0 = (tid & 15) << 3;
    int flat = 0;
    for (int l = 0; l < 3; l++) {
        const float* Bp = (l == 0) ? b1 : ((l == 1) ? b2 : b3);
        unsigned long long acc[8][4];
        #pragma unroll
        for (int o = 0; o < 8; o++)
            #pragma unroll
            for (int j = 0; j < 4; j++) acc[o][j] = 0ull;

        for (int cch = 0; cch < NCH; cch++) {
            int cur = flat & 1;
            bool hasNext = (flat < 32);
            float4 wpre0, wpre1, wpre2;
            if (hasNext) {
                const float4* wg = (const float4*)(Wd + (size_t)(flat+1)*WCHUNK);
                wpre0 = wg[tid]; wpre1 = wg[tid+256]; wpre2 = wg[tid+512];
            }
            float2* Wc = (float2*)Wsm + cur*WCHUNK;
            const float* Xc = Xs + cch*KCH*XS_STRIDE;
            #pragma unroll
            for (int kk = 0; kk < KCH; kk++) {
                const ulonglong2* wrow = (const ulonglong2*)(Wc + kk*128 + o0);
                const ulonglong2* xrow = (const ulonglong2*)(Xc + kk*XS_STRIDE + p0);
                ulonglong2 w01 = wrow[0], w23 = wrow[1], w45 = wrow[2], w67 = wrow[3];
                ulonglong2 xA = xrow[0], xB = xrow[1];
                unsigned long long w[8] = {w01.x, w01.y, w23.x, w23.y, w45.x, w45.y, w67.x, w67.y};
                unsigned long long x[4] = {xA.x, xA.y, xB.x, xB.y};
                #pragma unroll
                for (int o = 0; o < 8; o++)
                    #pragma unroll
                    for (int j = 0; j < 4; j++)
                        acc[o][j] = ffma2(w[o], x[j], acc[o][j]);
            }
            if (hasNext) {
                __syncthreads();
                float4* wd = (float4*)((float2*)Wsm + (cur^1)*WCHUNK);
                wd[tid] = wpre0; wd[tid+256] = wpre1; wd[tid+512] = wpre2;
                __syncthreads();
            }
            flat++;
        }
        if (l == 2) __syncthreads();
        #pragma unroll
        for (int o = 0; o < 8; o++) {
            float bo = __ldg(&Bp[o0 + o]);
            float r[8];
            #pragma unroll
            for (int j = 0; j < 4; j++) unpack2(acc[o][j], r[2*j], r[2*j+1]);
            float4 A, Bv;
            A.x  = fmaxf(r[0]+bo, 0.f); A.y  = fmaxf(r[1]+bo, 0.f);
            A.z  = fmaxf(r[2]+bo, 0.f); A.w  = fmaxf(r[3]+bo, 0.f);
            Bv.x = fmaxf(r[4]+bo, 0.f); Bv.y = fmaxf(r[5]+bo, 0.f);
            Bv.z = fmaxf(r[6]+bo, 0.f); Bv.w = fmaxf(r[7]+bo, 0.f);
            *(float4*)(Xs + (o0+o)*XS_STRIDE + p0)     = A;
            *(float4*)(Xs + (o0+o)*XS_STRIDE + p0 + 4) = Bv;
        }
        __syncthreads();
    }

    if (tid < 128) {
        int gp = pBase + tid;
        float a0 = 0.f, a1 = 0.f, a2 = 0.f;
        for (int k = 0; k < KIN; k++) {
            float xv = Xs[k*XS_STRIDE + tid];
            a0 += __ldg(&wph[k])*xv;
            a1 += __ldg(&wph[KIN + k])*xv;
            a2 += __ldg(&wph[2*KIN + k])*xv;
        }
        int id = g_idx[gp];
        sem[(size_t)(n*NCLS + 0)*HW + id] = a0 + __ldg(&bph[0]);
        sem[(size_t)(n*NCLS + 1)*HW + id] = a1 + __ldg(&bph[1]);
        sem[(size_t)(n*NCLS + 2)*HW + id] = a2 + __ldg(&bph[2]);
    }
}

// ---------------- launch ----------------
extern "C" void kernel_launch(void* const* d_in, const int* in_sizes, int n_in,
                              void* d_out, int out_size) {
    const float* coarse = (const float*)d_in[0];
    const float* feat   = (const float*)d_in[1];
    const float* w1 = (const float*)d_in[2];
    const float* b1 = (const float*)d_in[3];
    const float* w2 = (const float*)d_in[4];
    const float* b2 = (const float*)d_in[5];
    const float* w3 = (const float*)d_in[6];
    const float* b3 = (const float*)d_in[7];
    const float* wp = (const float*)d_in[8];
    const float* bp = (const float*)d_in[9];
    float* out = (float*)d_out;

    float* sem256;
    float2* Wd;
    cudaGetSymbolAddress((void**)&sem256, g_sem256);
    cudaGetSymbolAddress((void**)&Wd, g_Wd);

    // side stream + events, created on first (uncaptured) call, reused thereafter
    static cudaStream_t sSide = nullptr;
    static cudaEvent_t evFork = nullptr, evJoin = nullptr;
    if (sSide == nullptr) {
        cudaStreamCreateWithFlags(&sSide, cudaStreamNonBlocking);
        cudaEventCreateWithFlags(&evFork, cudaEventDisableTiming);
        cudaEventCreateWithFlags(&evJoin, cudaEventDisableTiming);
    }

    const int MLPSMEM = (FCK*XS_STRIDE + 2*WCHUNK*2) * 4;   // 94,272 B
    cudaFuncSetAttribute(mlp_kernel, cudaFuncAttributeMaxDynamicSharedMemorySize, MLPSMEM);

    // fork: transpose on side stream, overlapped with prep + step-0 selection
    cudaEventRecord(evFork, 0);
    cudaStreamWaitEvent(sSide, evFork, 0);
    transpose_kernel<<<dim3(2048, 4, 4), dim3(32, 8), 0, sSide>>>(feat);
    cudaEventRecord(evJoin, sSide);

    prep_kernel<<<256, 256>>>(w1, w2, w3);

    for (int step = 0; step < 2; step++) {
        int logW = (step == 0) ? 8 : 9;
        int HW   = 1 << (2*logW);
        const float* semIn = (step == 0) ? coarse : sem256;
        float* semOut      = (step == 0) ? sem256 : out;

        upsample_sel<<<dim3(HW/1024, NB), 256>>>(semIn, semOut, logW);
        compact_sel<<<dim3(HW/4096, NB), 1024>>>(HW);

        if (step == 0) cudaStreamWaitEvent(0, evJoin, 0);   // join transpose before first mlp
        mlp_kernel<<<PTOT/128, 256, MLPSMEM>>>(coarse, Wd, b1, b2, b3, wp, bp, semOut, HW, logW);
    }
}

// round 10
// speedup vs baseline: 1.1235x; 1.1235x over previous
#include <cuda_runtime.h>
#include <math.h>

typedef unsigned int       u32;
typedef unsigned long long u64;
typedef unsigned short     u16;

#define NB   4
#define NCLS 3
#define FH   256
#define CH   128
#define NIN  128
#define KIN  131
#define FCK  132
#define KCH  12
#define NCH  11
#define PPB  8192
#define PTOT 32768
#define KEYSTRIDE 262144
#define TOPK 8192u
#define XS_STRIDE 132
#define WCHUNK 1536

// step-2 mma.sync geometry: K padded to 144 bf16 = 72 u32 pairs
#define KP   72
#define WPLANE (128*144)          // u16 per plane

// ---------------- scratch ----------------
__device__ float        g_featT[(size_t)NB*FH*FH*NIN];
__device__ float        g_sem256[NB*NCLS*256*256];
__device__ unsigned int g_keys[NB*KEYSTRIDE];
__device__ unsigned int g_hist2[NB*4096];
__device__ unsigned long long g_cand[(size_t)NB*KEYSTRIDE];
__device__ int          g_bstar[NB];
__device__ int          g_kRem[NB];
__device__ int          g_selCount[NB];
__device__ int          g_candCount[NB];
__device__ int          g_done1[NB];
__device__ int          g_done2[NB];
__device__ int          g_idx[PTOT];
__device__ float2       g_Wd[(size_t)3*FCK*NIN];
__device__ __align__(16) u16 g_Wbf2[3*2*WPLANE];   // [layer][hi|lo][out][k]

__device__ __forceinline__ unsigned int fkey(float f) {
    unsigned int u = __float_as_uint(f);
    return (u & 0x80000000u) ? ~u : (u | 0x80000000u);
}
__device__ __forceinline__ unsigned long long ffma2(unsigned long long a, unsigned long long b, unsigned long long c) {
    unsigned long long d;
    asm("fma.rn.f32x2 %0, %1, %2, %3;" : "=l"(d) : "l"(a), "l"(b), "l"(c));
    return d;
}
__device__ __forceinline__ void unpack2(unsigned long long v, float& lo, float& hi) {
    unsigned int a, b;
    asm("mov.b64 {%0,%1}, %2;" : "=r"(a), "=r"(b) : "l"(v));
    lo = __uint_as_float(a); hi = __uint_as_float(b);
}

// ---------------- bf16 helpers (no cuda_bf16.h) ----------------
__device__ __forceinline__ u32 pack_bf16x2(float lo_val, float hi_val) {
    u32 r;
    asm("cvt.rn.bf16x2.f32 %0, %1, %2;" : "=r"(r) : "f"(hi_val), "f"(lo_val));
    return r;  // low 16 = bf16(lo_val), high 16 = bf16(hi_val)
}
__device__ __forceinline__ float bf16lo_f(u32 p) { return __uint_as_float(p << 16); }
__device__ __forceinline__ float bf16hi_f(u32 p) { return __uint_as_float(p & 0xFFFF0000u); }

// mma.sync m16n8k16 bf16: D(f32) += A(bf16) * B(bf16)
__device__ __forceinline__ void mma16816(float* d, u32 a0, u32 a1, u32 a2, u32 a3, u32 b0, u32 b1) {
    asm volatile("mma.sync.aligned.m16n8k16.row.col.f32.bf16.bf16.f32 {%0,%1,%2,%3}, {%4,%5,%6,%7}, {%8,%9}, {%0,%1,%2,%3};" : "+f"(d[0]), "+f"(d[1]), "+f"(d[2]), "+f"(d[3]) : "r"(a0), "r"(a1), "r"(a2), "r"(a3), "r"(b0), "r"(b1));
}

// ---------------- one-time prep ----------------
__global__ void prep_kernel(const float* __restrict__ w1, const float* __restrict__ w2,
                            const float* __restrict__ w3) {
    int i = blockIdx.x*blockDim.x + threadIdx.x;
    int stride = gridDim.x*blockDim.x;
    for (int j = i; j < NB*4096; j += stride) g_hist2[j] = 0;
    if (i < NB) { g_done1[i] = 0; g_done2[i] = 0; g_selCount[i] = 0; g_candCount[i] = 0; }
    for (int j = i; j < 3*FCK*NIN; j += stride) {
        int l = j / (FCK*NIN); int r = j - l*(FCK*NIN);
        int k = r >> 7; int o = r & 127;
        const float* w = (l == 0) ? w1 : ((l == 1) ? w2 : w3);
        float v = (k < KIN) ? w[o*KIN + k] : 0.f;
        g_Wd[j] = make_float2(v, v);
    }
    for (int j = i; j < 3*WPLANE; j += stride) {
        int l = j / WPLANE; int r = j - l*WPLANE;
        int o = r / 144; int k = r - o*144;
        const float* w = (l == 0) ? w1 : ((l == 1) ? w2 : w3);
        float v = (k < KIN) ? w[o*KIN + k] : 0.f;
        u32 hp = pack_bf16x2(v, 0.f);
        u16 hbits = (u16)(hp & 0xFFFFu);
        float hf = __uint_as_float((u32)hbits << 16);
        u32 lp = pack_bf16x2(v - hf, 0.f);
        g_Wbf2[(l*2 + 0)*WPLANE + r] = hbits;
        g_Wbf2[(l*2 + 1)*WPLANE + r] = (u16)(lp & 0xFFFFu);
    }
}

// ---------------- features NCHW -> NHWC ----------------
__global__ void transpose_kernel(const float* __restrict__ f) {
    __shared__ float tile[32][33];
    int n = blockIdx.z;
    int pix0 = blockIdx.x * 32;
    int c0   = blockIdx.y * 32;
    int tx = threadIdx.x, ty = threadIdx.y;
    #pragma unroll
    for (int i = ty; i < 32; i += 8)
        tile[i][tx] = f[(size_t)(n*NIN + c0 + i)*(FH*FH) + pix0 + tx];
    __syncthreads();
    #pragma unroll
    for (int i = ty; i < 32; i += 8)
        g_featT[(size_t)(n*(FH*FH) + pix0 + i)*NIN + c0 + tx] = tile[tx][i];
}

// ---------------- K1: upsample + keys + hist; last block resolves ----------------
__global__ void upsample_sel(const float* __restrict__ in, float* __restrict__ out, int logW) {
    __shared__ unsigned int sh[4096];
    __shared__ unsigned int wsum[8];
    __shared__ int sh_last;
    int n = blockIdx.y;
    int t = threadIdx.x;
    for (int i = t; i < 4096; i += 256) sh[i] = 0;
    __syncthreads();
    int W = 1 << logW, Hin = W >> 1;
    int HW = W << logW;
    for (int pix = blockIdx.x*256 + t; pix < HW; pix += gridDim.x*256) {
        int y = pix >> logW;  int x = pix & (W - 1);
        int y0 = (y - 1) >> 1, x0 = (x - 1) >> 1;
        float wy1 = (y & 1) ? 0.25f : 0.75f;
        float wx1 = (x & 1) ? 0.25f : 0.75f;
        int y1 = y0 + 1, x1 = x0 + 1;
        int xa = (x0 < 0) ? 0 : x0;
        int xb = (x1 > Hin-1) ? Hin-1 : x1;
        float v[NCLS];
        #pragma unroll
        for (int c = 0; c < NCLS; c++) {
            const float* p = in + (size_t)(n*NCLS + c)*Hin*Hin;
            float colA, colB;
            if (y0 < 0)            { colA = p[xa];               colB = p[xb]; }
            else if (y1 > Hin - 1) { colA = p[(Hin-1)*Hin + xa]; colB = p[(Hin-1)*Hin + xb]; }
            else {
                colA = (1.f - wy1)*p[y0*Hin + xa] + wy1*p[y1*Hin + xa];
                colB = (1.f - wy1)*p[y0*Hin + xb] + wy1*p[y1*Hin + xb];
            }
            float vv;
            if (x0 < 0)            vv = colA;
            else if (x1 > Hin - 1) vv = colB;
            else                   vv = (1.f - wx1)*colA + wx1*colB;
            v[c] = vv;
            out[(size_t)(n*NCLS + c)*HW + pix] = vv;
        }
        float hi = fmaxf(v[0], v[1]), lo = fminf(v[0], v[1]);
        float m1 = fmaxf(hi, v[2]);
        float m2 = fmaxf(lo, fminf(hi, v[2]));
        unsigned int key = fkey(m2 - m1);
        g_keys[n*KEYSTRIDE + pix] = key;
        atomicAdd(&sh[key >> 20], 1u);
    }
    __syncthreads();
    for (int i = t; i < 4096; i += 256) {
        unsigned int v = sh[i];
        if (v) atomicAdd(&g_hist2[n*4096 + i], v);
    }
    __threadfence();
    if (t == 0) {
        int old = atomicAdd(&g_done1[n], 1);
        sh_last = (old == (int)gridDim.x - 1);
    }
    __syncthreads();
    if (!sh_last) return;
    unsigned int* gh = g_hist2 + n*4096;
    int lane = t & 31, wrp = t >> 5;
    int base = 4095 - (t << 4);
    unsigned int h[16];
    unsigned int sum = 0;
    #pragma unroll
    for (int j = 0; j < 16; j++) { h[j] = gh[base - j]; sum += h[j]; }
    unsigned int v = sum;
    #pragma unroll
    for (int off = 1; off < 32; off <<= 1) {
        unsigned int u = __shfl_up_sync(0xffffffffu, v, off);
        if (lane >= off) v += u;
    }
    if (lane == 31) wsum[wrp] = v;
    __syncthreads();
    if (wrp == 0 && lane < 8) {
        unsigned int w = wsum[lane];
        #pragma unroll
        for (int off = 1; off < 8; off <<= 1) {
            unsigned int u = __shfl_up_sync(0xffu, w, off);
            if (lane >= off) w += u;
        }
        wsum[lane] = w;
    }
    __syncthreads();
    unsigned int incl = v + (wrp ? wsum[wrp-1] : 0u);
    unsigned int excl = incl - sum;
    if (excl < TOPK && TOPK <= incl) {
        unsigned int c = excl;
        #pragma unroll
        for (int j = 0; j < 16; j++) {
            if (c + h[j] >= TOPK) { g_bstar[n] = base - j; g_kRem[n] = (int)(TOPK - c); break; }
            c += h[j];
        }
    }
    #pragma unroll
    for (int j = 0; j < 16; j++) gh[base - j] = 0;
    if (t == 0) { g_selCount[n] = 0; g_candCount[n] = 0; g_done1[n] = 0; }
}

// ---------------- K2: compact + exact candidate radix select ----------------
__global__ void __launch_bounds__(1024)
compact_sel(int HW) {
    __shared__ unsigned int hist[1024];
    __shared__ unsigned int wsum[32];
    __shared__ int sh_d, sh_last;
    __shared__ unsigned int sh_sub;
    int n = blockIdx.y;
    int t = threadIdx.x;
    int lane = t & 31, wrp = t >> 5;
    int bstar = g_bstar[n];
    const unsigned int* keys = g_keys + n*KEYSTRIDE;
    unsigned long long* cand = g_cand + (size_t)n*KEYSTRIDE;
    for (int i = blockIdx.x*1024 + t; i < HW; i += gridDim.x*1024) {
        unsigned int key = keys[i];
        int b = (int)(key >> 20);
        if (b > bstar) {
            int p = atomicAdd(&g_selCount[n], 1);
            g_idx[n*PPB + p] = i;
        } else if (b == bstar) {
            int p = atomicAdd(&g_candCount[n], 1);
            cand[p] = (((unsigned long long)(key & 0xFFFFFu)) << 18) | (unsigned int)((~i) & 0x3FFFF);
        }
    }
    __threadfence();
    if (t == 0) {
        int old = atomicAdd(&g_done2[n], 1);
        sh_last = (old == (int)gridDim.x - 1);
    }
    __syncthreads();
    if (!sh_last) return;
    int m = g_candCount[n];
    unsigned int need = (unsigned int)g_kRem[n];
    unsigned long long prefix = 0, pmask = 0;
    if (m > (int)need) {
        #pragma unroll
        for (int pass = 0; pass < 4; pass++) {
            int shift = 30 - 10*pass;
            hist[t] = 0;
            __syncthreads();
            for (int i = t; i < m; i += 1024) {
                unsigned long long c = cand[i];
                if ((c & pmask) == prefix)
                    atomicAdd(&hist[(unsigned int)(c >> shift) & 1023u], 1u);
            }
            __syncthreads();
            unsigned int val = hist[1023 - t];
            unsigned int v = val;
            #pragma unroll
            for (int off = 1; off < 32; off <<= 1) {
                unsigned int u = __shfl_up_sync(0xffffffffu, v, off);
                if (lane >= off) v += u;
            }
            if (lane == 31) wsum[wrp] = v;
            __syncthreads();
            if (wrp == 0) {
                unsigned int w = wsum[lane];
                #pragma unroll
                for (int off = 1; off < 32; off <<= 1) {
                    unsigned int u = __shfl_up_sync(0xffffffffu, w, off);
                    if (lane >= off) w += u;
                }
                wsum[lane] = w;
            }
            __syncthreads();
            unsigned int incl = v + (wrp ? wsum[wrp-1] : 0u);
            unsigned int excl = incl - val;
            if (excl < need && need <= incl) { sh_d = 1023 - t; sh_sub = excl; }
            __syncthreads();
            need -= sh_sub;
            prefix |= ((unsigned long long)(unsigned int)sh_d) << shift;
            pmask  |= 1023ull << shift;
            __syncthreads();
        }
    }
    for (int i = t; i < m; i += 1024) {
        unsigned long long c = cand[i];
        if (c >= prefix) {
            int p = atomicAdd(&g_selCount[n], 1);
            g_idx[n*PPB + p] = (int)((~c) & 0x3FFFF);
        }
    }
    if (t == 0) g_done2[n] = 0;
}

// ---------------- step-1 MLP (exact fp32 FFMA2) ----------------
__global__ void __launch_bounds__(256, 2)
mlp_kernel(const float* __restrict__ coarse, const float2* __restrict__ Wd,
           const float* __restrict__ b1, const float* __restrict__ b2, const float* __restrict__ b3,
           const float* __restrict__ wph, const float* __restrict__ bph,
           float* __restrict__ sem, int HW, int logW) {
    extern __shared__ float dynsm[];
    float* Xs  = dynsm;
    float* Wsm = dynsm + FCK*XS_STRIDE;
    __shared__ int   sx0[128], sy0[128];
    __shared__ float sw0[128], sw1[128], sw2[128], sw3[128], spx[128], spy[128];

    int tid = threadIdx.x, lane = tid & 31, wrp = tid >> 5;
    int pBase = blockIdx.x * 128;
    int n = pBase >> 13;

    if (tid < 128) {
        int id = g_idx[pBase + tid];
        int W = 1 << logW;
        float inv = 1.f / (float)W;
        float px = ((float)(id & (W-1)) + 0.5f) * inv;
        float py = ((float)(id >> logW) + 0.5f) * inv;
        spx[tid] = px; spy[tid] = py;
        float fx = px * 256.f - 0.5f, fy = py * 256.f - 0.5f;
        float fx0 = floorf(fx), fy0 = floorf(fy);
        float wx1 = fx - fx0, wy1 = fy - fy0;
        sx0[tid] = (int)fx0; sy0[tid] = (int)fy0;
        sw0[tid] = (1.f-wx1)*(1.f-wy1);
        sw1[tid] = wx1*(1.f-wy1);
        sw2[tid] = (1.f-wx1)*wy1;
        sw3[tid] = wx1*wy1;
    }
    __syncthreads();

    const float* fbase = g_featT + (size_t)n*FH*FH*NIN;
    float* tile = Wsm;
    int off = lane << 2;
    for (int s = 0; s < 4; s++) {
        #pragma unroll
        for (int it = 0; it < 4; it++) {
            int j = wrp + it*8;
            int jg = s*32 + j;
            int x0 = sx0[jg], y0 = sy0[jg];
            bool xv0 = (x0 >= 0), xv1 = (x0+1 < FH), yv0 = (y0 >= 0), yv1 = (y0+1 < FH);
            float a0 = 0.f, a1 = 0.f, a2 = 0.f, a3 = 0.f;
            if (xv0 && yv0) { float w = sw0[jg]; float4 v = *(const float4*)(fbase + (size_t)((y0  )*FH + x0  )*NIN + off);
                              a0 += w*v.x; a1 += w*v.y; a2 += w*v.z; a3 += w*v.w; }
            if (xv1 && yv0) { float w = sw1[jg]; float4 v = *(const float4*)(fbase + (size_t)((y0  )*FH + x0+1)*NIN + off);
                              a0 += w*v.x; a1 += w*v.y; a2 += w*v.z; a3 += w*v.w; }
            if (xv0 && yv1) { float w = sw2[jg]; float4 v = *(const float4*)(fbase + (size_t)((y0+1)*FH + x0  )*NIN + off);
                              a0 += w*v.x; a1 += w*v.y; a2 += w*v.z; a3 += w*v.w; }
            if (xv1 && yv1) { float w = sw3[jg]; float4 v = *(const float4*)(fbase + (size_t)((y0+1)*FH + x0+1)*NIN + off);
                              a0 += w*v.x; a1 += w*v.y; a2 += w*v.z; a3 += w*v.w; }
            tile[(off+0)*33 + j] = a0; tile[(off+1)*33 + j] = a1;
            tile[(off+2)*33 + j] = a2; tile[(off+3)*33 + j] = a3;
        }
        if (tid < 96) {
            int j = tid / 3, cc = tid - (tid/3)*3;
            int jg = s*32 + j;
            float cx = spx[jg]*128.f - 0.5f, cy = spy[jg]*128.f - 0.5f;
            float cx0f = floorf(cx), cy0f = floorf(cy);
            int x0 = (int)cx0f, y0 = (int)cy0f;
            float wx1 = cx - cx0f, wy1 = cy - cy0f;
            const float* p = coarse + (size_t)(n*NCLS + cc)*CH*CH;
            float acc = 0.f;
            if (x0 >= 0   && y0 >= 0  ) acc += (1.f-wx1)*(1.f-wy1)*p[y0*CH + x0];
            if (x0+1 < CH && y0 >= 0  ) acc += wx1*(1.f-wy1)*p[y0*CH + x0+1];
            if (x0 >= 0   && y0+1 < CH) acc += (1.f-wx1)*wy1*p[(y0+1)*CH + x0];
            if (x0+1 < CH && y0+1 < CH) acc += wx1*wy1*p[(y0+1)*CH + x0+1];
            tile[(NIN+cc)*33 + j] = acc;
        }
        __syncthreads();
        for (int idx = tid; idx < 132*32; idx += 256) {
            int r = idx >> 5, j = idx & 31;
            float v = (r < KIN) ? tile[r*33 + j] : 0.f;
            Xs[r*XS_STRIDE + s*32 + j] = v;
        }
        __syncthreads();
    }

    {
        const float4* wg = (const float4*)Wd;
        float4* wd = (float4*)Wsm;
        wd[tid] = wg[tid]; wd[tid+256] = wg[tid+256]; wd[tid+512] = wg[tid+512];
    }
    __syncthreads();

    int o0 = (tid >> 4) << 3;
    int p0 = (tid & 15) << 3;
    int flat = 0;
    for (int l = 0; l < 3; l++) {
        const float* Bp = (l == 0) ? b1 : ((l == 1) ? b2 : b3);
        unsigned long long acc[8][4];
        #pragma unroll
        for (int o = 0; o < 8; o++)
            #pragma unroll
            for (int j = 0; j < 4; j++) acc[o][j] = 0ull;

        for (int cch = 0; cch < NCH; cch++) {
            int cur = flat & 1;
            bool hasNext = (flat < 32);
            float4 wpre0, wpre1, wpre2;
            if (hasNext) {
                const float4* wg = (const float4*)(Wd + (size_t)(flat+1)*WCHUNK);
                wpre0 = wg[tid]; wpre1 = wg[tid+256]; wpre2 = wg[tid+512];
            }
            float2* Wc = (float2*)Wsm + cur*WCHUNK;
            const float* Xc = Xs + cch*KCH*XS_STRIDE;
            #pragma unroll
            for (int kk = 0; kk < KCH; kk++) {
                const ulonglong2* wrow = (const ulonglong2*)(Wc + kk*128 + o0);
                const ulonglong2* xrow = (const ulonglong2*)(Xc + kk*XS_STRIDE + p0);
                ulonglong2 w01 = wrow[0], w23 = wrow[1], w45 = wrow[2], w67 = wrow[3];
                ulonglong2 xA = xrow[0], xB = xrow[1];
                unsigned long long w[8] = {w01.x, w01.y, w23.x, w23.y, w45.x, w45.y, w67.x, w67.y};
                unsigned long long x[4] = {xA.x, xA.y, xB.x, xB.y};
                #pragma unroll
                for (int o = 0; o < 8; o++)
                    #pragma unroll
                    for (int j = 0; j < 4; j++)
                        acc[o][j] = ffma2(w[o], x[j], acc[o][j]);
            }
            if (hasNext) {
                __syncthreads();
                float4* wd = (float4*)((float2*)Wsm + (cur^1)*WCHUNK);
                wd[tid] = wpre0; wd[tid+256] = wpre1; wd[tid+512] = wpre2;
                __syncthreads();
            }
            flat++;
        }
        if (l == 2) __syncthreads();
        #pragma unroll
        for (int o = 0; o < 8; o++) {
            float bo = __ldg(&Bp[o0 + o]);
            float r[8];
            #pragma unroll
            for (int j = 0; j < 4; j++) unpack2(acc[o][j], r[2*j], r[2*j+1]);
            float4 A, Bv;
            A.x  = fmaxf(r[0]+bo, 0.f); A.y  = fmaxf(r[1]+bo, 0.f);
            A.z  = fmaxf(r[2]+bo, 0.f); A.w  = fmaxf(r[3]+bo, 0.f);
            Bv.x = fmaxf(r[4]+bo, 0.f); Bv.y = fmaxf(r[5]+bo, 0.f);
            Bv.z = fmaxf(r[6]+bo, 0.f); Bv.w = fmaxf(r[7]+bo, 0.f);
            *(float4*)(Xs + (o0+o)*XS_STRIDE + p0)     = A;
            *(float4*)(Xs + (o0+o)*XS_STRIDE + p0 + 4) = Bv;
        }
        __syncthreads();
    }

    if (tid < 128) {
        int gp = pBase + tid;
        float a0 = 0.f, a1 = 0.f, a2 = 0.f;
        for (int k = 0; k < KIN; k++) {
            float xv = Xs[k*XS_STRIDE + tid];
            a0 += __ldg(&wph[k])*xv;
            a1 += __ldg(&wph[KIN + k])*xv;
            a2 += __ldg(&wph[2*KIN + k])*xv;
        }
        int id = g_idx[gp];
        sem[(size_t)(n*NCLS + 0)*HW + id] = a0 + __ldg(&bph[0]);
        sem[(size_t)(n*NCLS + 1)*HW + id] = a1 + __ldg(&bph[1]);
        sem[(size_t)(n*NCLS + 2)*HW + id] = a2 + __ldg(&bph[2]);
    }
}

// ---------------- step-2 MLP: mma.sync bf16 hi/lo split ----------------
// smem (bytes): XhiP 0..36864, XloP ..73728, WhiP ..110592, WloP ..147456, misc after
#define XHIP_O 0
#define XLOP_O 36864
#define WHIP_O 73728
#define MISC_O 147456
#define MLP2SMEM (147456 + 5200)

__global__ void __launch_bounds__(256, 1)
mlp2_kernel(const float* __restrict__ coarse,
            const float* __restrict__ b1, const float* __restrict__ b2, const float* __restrict__ b3,
            const float* __restrict__ wph, const float* __restrict__ bph,
            float* __restrict__ sem, int HW, int logW) {
    extern __shared__ float dynsm[];
    char* smc = (char*)dynsm;
    u32* XhiP = (u32*)(smc + XHIP_O);   // [128][72] bf16 pairs
    u32* XloP = (u32*)(smc + XLOP_O);
    u32* WhiP = (u32*)(smc + WHIP_O);   // hi plane then lo plane contiguous
    u32* WloP = WhiP + 128*KP;
    float* bias_s  = (float*)(smc + MISC_O);          // 128
    float* wps     = (float*)(smc + MISC_O + 512);    // 393 (pad 396)
    float* hsum    = (float*)(smc + MISC_O + 2096);   // 3*128
    float* scoarse = (float*)(smc + MISC_O + 3632);   // 3*128

    __shared__ int   sx0[128], sy0[128];
    __shared__ float sw0[128], sw1[128], sw2[128], sw3[128];

    int tid = threadIdx.x, lane = tid & 31, wrp = tid >> 5;
    int pBase = blockIdx.x * 128;
    int n = pBase >> 13;

    // zero X hi+lo (73728 B = 4608 float4)
    {
        float4 z = make_float4(0.f, 0.f, 0.f, 0.f);
        float4* xz = (float4*)(smc + XHIP_O);
        #pragma unroll
        for (int q = 0; q < 18; q++) xz[tid + 256*q] = z;
    }
    if (tid < 128) {
        int id = g_idx[pBase + tid];
        int W = 1 << logW;
        float inv = 1.f / (float)W;
        float px = ((float)(id & (W-1)) + 0.5f) * inv;
        float py = ((float)(id >> logW) + 0.5f) * inv;
        float fx = px * 256.f - 0.5f, fy = py * 256.f - 0.5f;
        float fx0 = floorf(fx), fy0 = floorf(fy);
        float wx1 = fx - fx0, wy1 = fy - fy0;
        sx0[tid] = (int)fx0; sy0[tid] = (int)fy0;
        sw0[tid] = (1.f-wx1)*(1.f-wy1);
        sw1[tid] = wx1*(1.f-wy1);
        sw2[tid] = (1.f-wx1)*wy1;
        sw3[tid] = wx1*wy1;
        float cx = px*128.f - 0.5f, cy = py*128.f - 0.5f;
        float cx0f = floorf(cx), cy0f = floorf(cy);
        int x0 = (int)cx0f, y0 = (int)cy0f;
        float cwx = cx - cx0f, cwy = cy - cy0f;
        #pragma unroll
        for (int cc = 0; cc < NCLS; cc++) {
            const float* p = coarse + (size_t)(n*NCLS + cc)*CH*CH;
            float acc = 0.f;
            if (x0 >= 0   && y0 >= 0  ) acc += (1.f-cwx)*(1.f-cwy)*p[y0*CH + x0];
            if (x0+1 < CH && y0 >= 0  ) acc += cwx*(1.f-cwy)*p[y0*CH + x0+1];
            if (x0 >= 0   && y0+1 < CH) acc += (1.f-cwx)*cwy*p[(y0+1)*CH + x0];
            if (x0+1 < CH && y0+1 < CH) acc += cwx*cwy*p[(y0+1)*CH + x0+1];
            scoarse[cc*128 + tid] = acc;
        }
    }
    for (int j = tid; j < 3*KIN; j += 256) wps[j] = wph[j];
    __syncthreads();

    // feature gather -> X bf16 hi/lo pairs (warp-per-point, lane = 4 channels = 2 pairs)
    const float* fbase = g_featT + (size_t)n*FH*FH*NIN;
    int ch0 = lane << 2;
    #pragma unroll 4
    for (int it = 0; it < 16; it++) {
        int pt = wrp + it*8;
        int x0 = sx0[pt], y0 = sy0[pt];
        bool xv0 = (x0 >= 0), xv1 = (x0+1 < FH), yv0 = (y0 >= 0), yv1 = (y0+1 < FH);
        float a0 = 0.f, a1 = 0.f, a2 = 0.f, a3 = 0.f;
        if (xv0 && yv0) { float w = sw0[pt]; float4 v = *(const float4*)(fbase + (size_t)((y0  )*FH + x0  )*NIN + ch0);
                          a0 += w*v.x; a1 += w*v.y; a2 += w*v.z; a3 += w*v.w; }
        if (xv1 && yv0) { float w = sw1[pt]; float4 v = *(const float4*)(fbase + (size_t)((y0  )*FH + x0+1)*NIN + ch0);
                          a0 += w*v.x; a1 += w*v.y; a2 += w*v.z; a3 += w*v.w; }
        if (xv0 && yv1) { float w = sw2[pt]; float4 v = *(const float4*)(fbase + (size_t)((y0+1)*FH + x0  )*NIN + ch0);
                          a0 += w*v.x; a1 += w*v.y; a2 += w*v.z; a3 += w*v.w; }
        if (xv1 && yv1) { float w = sw3[pt]; float4 v = *(const float4*)(fbase + (size_t)((y0+1)*FH + x0+1)*NIN + ch0);
                          a0 += w*v.x; a1 += w*v.y; a2 += w*v.z; a3 += w*v.w; }
        u32 hA = pack_bf16x2(a0, a1);
        u32 hB = pack_bf16x2(a2, a3);
        u32 lA = pack_bf16x2(a0 - bf16lo_f(hA), a1 - bf16hi_f(hA));
        u32 lB = pack_bf16x2(a2 - bf16lo_f(hB), a3 - bf16hi_f(hB));
        int pp = pt*KP + (lane << 1);
        *(uint2*)(XhiP + pp) = make_uint2(hA, hB);
        *(uint2*)(XloP + pp) = make_uint2(lA, lB);
    }
    // coarse -> pairs 64 (k128,k129) and 65 (k130, 0); head coarse terms + bias -> hsum
    if (tid < 128) {
        float c0 = scoarse[tid], c1 = scoarse[128 + tid], c2 = scoarse[256 + tid];
        u32 h64 = pack_bf16x2(c0, c1);
        u32 l64 = pack_bf16x2(c0 - bf16lo_f(h64), c1 - bf16hi_f(h64));
        u32 h65 = pack_bf16x2(c2, 0.f);
        u32 l65 = pack_bf16x2(c2 - bf16lo_f(h65), 0.f);
        *(uint2*)(XhiP + tid*KP + 64) = make_uint2(h64, h65);
        *(uint2*)(XloP + tid*KP + 64) = make_uint2(l64, l65);
        #pragma unroll
        for (int c = 0; c < NCLS; c++)
            hsum[c*128 + tid] = wps[c*KIN + 128]*c0 + wps[c*KIN + 129]*c1 + wps[c*KIN + 130]*c2 + __ldg(&bph[c]);
    }
    __syncthreads();

    int g = lane >> 2;     // groupID 0..7
    int tig = lane & 3;
    int m0 = wrp * 16;
    int rA = (m0 + g)*KP;
    int rB = (m0 + g + 8)*KP;

    for (int l = 0; l < 3; l++) {
        // stage W hi+lo planes (73728 B contiguous)
        {
            const float4* wsrc = (const float4*)(g_Wbf2 + (size_t)l*2*WPLANE);
            float4* wdst = (float4*)WhiP;
            #pragma unroll
            for (int q = 0; q < 18; q++) wdst[tid + 256*q] = wsrc[tid + 256*q];
        }
        const float* Bp = (l == 0) ? b1 : ((l == 1) ? b2 : b3);
        if (tid < 128) bias_s[tid] = __ldg(&Bp[tid]);
        __syncthreads();

        float acc[16][4];
        #pragma unroll
        for (int nt = 0; nt < 16; nt++) {
            acc[nt][0] = 0.f; acc[nt][1] = 0.f; acc[nt][2] = 0.f; acc[nt][3] = 0.f;
        }
        for (int ks = 0; ks < 9; ks++) {
            int kp = ks*8 + tig;
            u32 ah0 = XhiP[rA + kp],     ah1 = XhiP[rB + kp];
            u32 ah2 = XhiP[rA + kp + 4], ah3 = XhiP[rB + kp + 4];
            u32 al0 = XloP[rA + kp],     al1 = XloP[rB + kp];
            u32 al2 = XloP[rA + kp + 4], al3 = XloP[rB + kp + 4];
            #pragma unroll
            for (int nt = 0; nt < 16; nt++) {
                int nrow = (nt*8 + g)*KP + kp;
                u32 bh0 = WhiP[nrow], bh1 = WhiP[nrow + 4];
                u32 bl0 = WloP[nrow], bl1 = WloP[nrow + 4];
                mma16816(acc[nt], ah0, ah1, ah2, ah3, bh0, bh1);
                mma16816(acc[nt], ah0, ah1, ah2, ah3, bl0, bl1);
                mma16816(acc[nt], al0, al1, al2, al3, bh0, bh1);
            }
        }
        __syncthreads();   // all warps done reading X/W before epilogue writes X

        // epilogue: bias + relu -> X hi/lo (outputs become next layer's k 0..127)
        #pragma unroll
        for (int nt = 0; nt < 16; nt++) {
            int col = nt*8 + (tig << 1);
            float bA = bias_s[col], bB = bias_s[col + 1];
            float v0 = fmaxf(acc[nt][0] + bA, 0.f);
            float v1 = fmaxf(acc[nt][1] + bB, 0.f);
            float v2 = fmaxf(acc[nt][2] + bA, 0.f);
            float v3 = fmaxf(acc[nt][3] + bB, 0.f);
            u32 hpA = pack_bf16x2(v0, v1);
            u32 lpA = pack_bf16x2(v0 - bf16lo_f(hpA), v1 - bf16hi_f(hpA));
            u32 hpB = pack_bf16x2(v2, v3);
            u32 lpB = pack_bf16x2(v2 - bf16lo_f(hpB), v3 - bf16hi_f(hpB));
            int idx = nt*4 + tig;
            XhiP[rA + idx] = hpA;  XloP[rA + idx] = lpA;
            XhiP[rB + idx] = hpB;  XloP[rB + idx] = lpB;
        }
        __syncthreads();
    }

    // head: per-thread point, reconstruct fp32 = hi + lo
    if (tid < 128) {
        float s0 = 0.f, s1 = 0.f, s2 = 0.f;
        const u32* hr = XhiP + tid*KP;
        const u32* lr = XloP + tid*KP;
        #pragma unroll 8
        for (int kp = 0; kp < 64; kp++) {
            u32 hp = hr[kp], lp = lr[kp];
            float x0 = bf16lo_f(hp) + bf16lo_f(lp);
            float x1 = bf16hi_f(hp) + bf16hi_f(lp);
            int k = kp << 1;
            s0 += wps[k]*x0 + wps[k+1]*x1;
            s1 += wps[KIN + k]*x0 + wps[KIN + k + 1]*x1;
            s2 += wps[2*KIN + k]*x0 + wps[2*KIN + k + 1]*x1;
        }
        int id = g_idx[pBase + tid];
        sem[(size_t)(n*NCLS + 0)*HW + id] = hsum[tid] + s0;
        sem[(size_t)(n*NCLS + 1)*HW + id] = hsum[128 + tid] + s1;
        sem[(size_t)(n*NCLS + 2)*HW + id] = hsum[256 + tid] + s2;
    }
}

// ---------------- launch ----------------
extern "C" void kernel_launch(void* const* d_in, const int* in_sizes, int n_in,
                              void* d_out, int out_size) {
    const float* coarse = (const float*)d_in[0];
    const float* feat   = (const float*)d_in[1];
    const float* w1 = (const float*)d_in[2];
    const float* b1 = (const float*)d_in[3];
    const float* w2 = (const float*)d_in[4];
    const float* b2 = (const float*)d_in[5];
    const float* w3 = (const float*)d_in[6];
    const float* b3 = (const float*)d_in[7];
    const float* wp = (const float*)d_in[8];
    const float* bp = (const float*)d_in[9];
    float* out = (float*)d_out;

    float* sem256;
    float2* Wd;
    cudaGetSymbolAddress((void**)&sem256, g_sem256);
    cudaGetSymbolAddress((void**)&Wd, g_Wd);

    static cudaStream_t sSide = nullptr;
    static cudaEvent_t evFork = nullptr, evJoin = nullptr;
    if (sSide == nullptr) {
        cudaStreamCreateWithFlags(&sSide, cudaStreamNonBlocking);
        cudaEventCreateWithFlags(&evFork, cudaEventDisableTiming);
        cudaEventCreateWithFlags(&evJoin, cudaEventDisableTiming);
    }

    const int FCSMEM = (FCK*XS_STRIDE + 2*WCHUNK*2) * 4;
    cudaFuncSetAttribute(mlp_kernel, cudaFuncAttributeMaxDynamicSharedMemorySize, FCSMEM);
    cudaFuncSetAttribute(mlp2_kernel, cudaFuncAttributeMaxDynamicSharedMemorySize, MLP2SMEM);

    cudaEventRecord(evFork, 0);
    cudaStreamWaitEvent(sSide, evFork, 0);
    transpose_kernel<<<dim3(2048, 4, 4), dim3(32, 8), 0, sSide>>>(feat);
    cudaEventRecord(evJoin, sSide);

    prep_kernel<<<256, 256>>>(w1, w2, w3);

    for (int step = 0; step < 2; step++) {
        int logW = (step == 0) ? 8 : 9;
        int HW   = 1 << (2*logW);
        const float* semIn = (step == 0) ? coarse : sem256;
        float* semOut      = (step == 0) ? sem256 : out;

        upsample_sel<<<dim3(HW/1024, NB), 256>>>(semIn, semOut, logW);
        compact_sel<<<dim3(HW/4096, NB), 1024>>>(HW);

        if (step == 0) {
            cudaStreamWaitEvent(0, evJoin, 0);
            mlp_kernel<<<PTOT/128, 256, FCSMEM>>>(coarse, Wd, b1, b2, b3, wp, bp, semOut, HW, logW);
        } else {
            mlp2_kernel<<<PTOT/128, 256, MLP2SMEM>>>(coarse, b1, b2, b3, wp, bp, semOut, HW, logW);
        }
    }
}

// round 11
// speedup vs baseline: 1.1361x; 1.0112x over previous
#include <cuda_runtime.h>
#include <math.h>

typedef unsigned int       u32;
typedef unsigned long long u64;
typedef unsigned short     u16;

#define NB   4
#define NCLS 3
#define FH   256
#define CH   128
#define NIN  128
#define KIN  131
#define PPB  8192
#define PTOT 32768
#define KEYSTRIDE 262144
#define TOPK 8192u

#define KP     72                 // 144 bf16 = 72 u32 pairs
#define WPLANE (128*144)          // u16 per plane
#define PLB    36864              // bytes per plane (128*72*4)
#define PLU    9216               // u32 per plane

// ---------------- scratch ----------------
__device__ float        g_featT[(size_t)NB*FH*FH*NIN];
__device__ float        g_sem256[NB*NCLS*256*256];
__device__ unsigned int g_keys[NB*KEYSTRIDE];
__device__ unsigned int g_hist2[NB*4096];
__device__ unsigned long long g_cand[(size_t)NB*KEYSTRIDE];
__device__ int          g_bstar[NB];
__device__ int          g_kRem[NB];
__device__ int          g_selCount[NB];
__device__ int          g_candCount[NB];
__device__ int          g_done1[NB];
__device__ int          g_done2[NB];
__device__ int          g_idx[PTOT];
__device__ __align__(16) u16 g_Wbf3[3*3*WPLANE];   // [layer][plane hi/mid/lo][out][k]

__device__ __forceinline__ unsigned int fkey(float f) {
    unsigned int u = __float_as_uint(f);
    return (u & 0x80000000u) ? ~u : (u | 0x80000000u);
}
__device__ __forceinline__ u32 pack_bf16x2(float lo_val, float hi_val) {
    u32 r;
    asm("cvt.rn.bf16x2.f32 %0, %1, %2;" : "=r"(r) : "f"(hi_val), "f"(lo_val));
    return r;
}
__device__ __forceinline__ float bf16lo_f(u32 p) { return __uint_as_float(p << 16); }
__device__ __forceinline__ float bf16hi_f(u32 p) { return __uint_as_float(p & 0xFFFF0000u); }

__device__ __forceinline__ void mma16816(float* d, u32 a0, u32 a1, u32 a2, u32 a3, u32 b0, u32 b1) {
    asm volatile("mma.sync.aligned.m16n8k16.row.col.f32.bf16.bf16.f32 {%0,%1,%2,%3}, {%4,%5,%6,%7}, {%8,%9}, {%0,%1,%2,%3};" : "+f"(d[0]), "+f"(d[1]), "+f"(d[2]), "+f"(d[3]) : "r"(a0), "r"(a1), "r"(a2), "r"(a3), "r"(b0), "r"(b1));
}

// ---------------- one-time prep: hist zero + 3-plane weight pack ----------------
__global__ void prep_kernel(const float* __restrict__ w1, const float* __restrict__ w2,
                            const float* __restrict__ w3) {
    int i = blockIdx.x*blockDim.x + threadIdx.x;
    int stride = gridDim.x*blockDim.x;
    for (int j = i; j < NB*4096; j += stride) g_hist2[j] = 0;
    if (i < NB) { g_done1[i] = 0; g_done2[i] = 0; g_selCount[i] = 0; g_candCount[i] = 0; }
    for (int j = i; j < 3*WPLANE; j += stride) {
        int l = j / WPLANE; int r = j - l*WPLANE;
        int o = r / 144; int k = r - o*144;
        const float* w = (l == 0) ? w1 : ((l == 1) ? w2 : w3);
        float v = (k < KIN) ? w[o*KIN + k] : 0.f;
        float rem = v;
        #pragma unroll
        for (int p = 0; p < 3; p++) {
            u32 pk = pack_bf16x2(rem, 0.f);
            u16 bits = (u16)(pk & 0xFFFFu);
            g_Wbf3[(l*3 + p)*WPLANE + r] = bits;
            rem -= __uint_as_float((u32)bits << 16);
        }
    }
}

// ---------------- features NCHW -> NHWC ----------------
__global__ void transpose_kernel(const float* __restrict__ f) {
    __shared__ float tile[32][33];
    int n = blockIdx.z;
    int pix0 = blockIdx.x * 32;
    int c0   = blockIdx.y * 32;
    int tx = threadIdx.x, ty = threadIdx.y;
    #pragma unroll
    for (int i = ty; i < 32; i += 8)
        tile[i][tx] = f[(size_t)(n*NIN + c0 + i)*(FH*FH) + pix0 + tx];
    __syncthreads();
    #pragma unroll
    for (int i = ty; i < 32; i += 8)
        g_featT[(size_t)(n*(FH*FH) + pix0 + i)*NIN + c0 + tx] = tile[tx][i];
}

// ---------------- K1: upsample + keys + hist; last block resolves ----------------
__global__ void upsample_sel(const float* __restrict__ in, float* __restrict__ out, int logW) {
    __shared__ unsigned int sh[4096];
    __shared__ unsigned int wsum[8];
    __shared__ int sh_last;
    int n = blockIdx.y;
    int t = threadIdx.x;
    for (int i = t; i < 4096; i += 256) sh[i] = 0;
    __syncthreads();
    int W = 1 << logW, Hin = W >> 1;
    int HW = W << logW;
    for (int pix = blockIdx.x*256 + t; pix < HW; pix += gridDim.x*256) {
        int y = pix >> logW;  int x = pix & (W - 1);
        int y0 = (y - 1) >> 1, x0 = (x - 1) >> 1;
        float wy1 = (y & 1) ? 0.25f : 0.75f;
        float wx1 = (x & 1) ? 0.25f : 0.75f;
        int y1 = y0 + 1, x1 = x0 + 1;
        int xa = (x0 < 0) ? 0 : x0;
        int xb = (x1 > Hin-1) ? Hin-1 : x1;
        float v[NCLS];
        #pragma unroll
        for (int c = 0; c < NCLS; c++) {
            const float* p = in + (size_t)(n*NCLS + c)*Hin*Hin;
            float colA, colB;
            if (y0 < 0)            { colA = p[xa];               colB = p[xb]; }
            else if (y1 > Hin - 1) { colA = p[(Hin-1)*Hin + xa]; colB = p[(Hin-1)*Hin + xb]; }
            else {
                colA = (1.f - wy1)*p[y0*Hin + xa] + wy1*p[y1*Hin + xa];
                colB = (1.f - wy1)*p[y0*Hin + xb] + wy1*p[y1*Hin + xb];
            }
            float vv;
            if (x0 < 0)            vv = colA;
            else if (x1 > Hin - 1) vv = colB;
            else                   vv = (1.f - wx1)*colA + wx1*colB;
            v[c] = vv;
            out[(size_t)(n*NCLS + c)*HW + pix] = vv;
        }
        float hi = fmaxf(v[0], v[1]), lo = fminf(v[0], v[1]);
        float m1 = fmaxf(hi, v[2]);
        float m2 = fmaxf(lo, fminf(hi, v[2]));
        unsigned int key = fkey(m2 - m1);
        g_keys[n*KEYSTRIDE + pix] = key;
        atomicAdd(&sh[key >> 20], 1u);
    }
    __syncthreads();
    for (int i = t; i < 4096; i += 256) {
        unsigned int v = sh[i];
        if (v) atomicAdd(&g_hist2[n*4096 + i], v);
    }
    __threadfence();
    if (t == 0) {
        int old = atomicAdd(&g_done1[n], 1);
        sh_last = (old == (int)gridDim.x - 1);
    }
    __syncthreads();
    if (!sh_last) return;
    unsigned int* gh = g_hist2 + n*4096;
    int lane = t & 31, wrp = t >> 5;
    int base = 4095 - (t << 4);
    unsigned int h[16];
    unsigned int sum = 0;
    #pragma unroll
    for (int j = 0; j < 16; j++) { h[j] = gh[base - j]; sum += h[j]; }
    unsigned int v = sum;
    #pragma unroll
    for (int off = 1; off < 32; off <<= 1) {
        unsigned int u = __shfl_up_sync(0xffffffffu, v, off);
        if (lane >= off) v += u;
    }
    if (lane == 31) wsum[wrp] = v;
    __syncthreads();
    if (wrp == 0 && lane < 8) {
        unsigned int w = wsum[lane];
        #pragma unroll
        for (int off = 1; off < 8; off <<= 1) {
            unsigned int u = __shfl_up_sync(0xffu, w, off);
            if (lane >= off) w += u;
        }
        wsum[lane] = w;
    }
    __syncthreads();
    unsigned int incl = v + (wrp ? wsum[wrp-1] : 0u);
    unsigned int excl = incl - sum;
    if (excl < TOPK && TOPK <= incl) {
        unsigned int c = excl;
        #pragma unroll
        for (int j = 0; j < 16; j++) {
            if (c + h[j] >= TOPK) { g_bstar[n] = base - j; g_kRem[n] = (int)(TOPK - c); break; }
            c += h[j];
        }
    }
    #pragma unroll
    for (int j = 0; j < 16; j++) gh[base - j] = 0;
    if (t == 0) { g_selCount[n] = 0; g_candCount[n] = 0; g_done1[n] = 0; }
}

// ---------------- K2: compact (warp-aggregated) + exact candidate radix select ----------------
__global__ void __launch_bounds__(1024)
compact_sel(int HW) {
    __shared__ unsigned int hist[1024];
    __shared__ unsigned int wsum[32];
    __shared__ int sh_d, sh_last;
    __shared__ unsigned int sh_sub;
    int n = blockIdx.y;
    int t = threadIdx.x;
    int lane = t & 31, wrp = t >> 5;
    int bstar = g_bstar[n];
    const unsigned int* keys = g_keys + n*KEYSTRIDE;
    unsigned long long* cand = g_cand + (size_t)n*KEYSTRIDE;
    for (int i = blockIdx.x*1024 + t; i < HW; i += gridDim.x*1024) {
        unsigned int key = keys[i];
        int b = (int)(key >> 20);
        bool isSel  = (b > bstar);
        bool isCand = (b == bstar);
        u32 mS = __ballot_sync(0xffffffffu, isSel);
        u32 mC = __ballot_sync(0xffffffffu, isCand);
        if (isSel) {
            int ldr = __ffs(mS) - 1;
            int base;
            if (lane == ldr) base = atomicAdd(&g_selCount[n], __popc(mS));
            base = __shfl_sync(mS, base, ldr);
            g_idx[n*PPB + base + __popc(mS & ((1u << lane) - 1u))] = i;
        }
        if (isCand) {
            int ldr = __ffs(mC) - 1;
            int base;
            if (lane == ldr) base = atomicAdd(&g_candCount[n], __popc(mC));
            base = __shfl_sync(mC, base, ldr);
            cand[base + __popc(mC & ((1u << lane) - 1u))] =
                (((unsigned long long)(key & 0xFFFFFu)) << 18) | (unsigned int)((~i) & 0x3FFFF);
        }
    }
    __threadfence();
    if (t == 0) {
        int old = atomicAdd(&g_done2[n], 1);
        sh_last = (old == (int)gridDim.x - 1);
    }
    __syncthreads();
    if (!sh_last) return;
    int m = g_candCount[n];
    unsigned int need = (unsigned int)g_kRem[n];
    unsigned long long prefix = 0, pmask = 0;
    if (m > (int)need) {
        #pragma unroll
        for (int pass = 0; pass < 4; pass++) {
            int shift = 30 - 10*pass;
            hist[t] = 0;
            __syncthreads();
            for (int i = t; i < m; i += 1024) {
                unsigned long long c = cand[i];
                if ((c & pmask) == prefix)
                    atomicAdd(&hist[(unsigned int)(c >> shift) & 1023u], 1u);
            }
            __syncthreads();
            unsigned int val = hist[1023 - t];
            unsigned int v = val;
            #pragma unroll
            for (int off = 1; off < 32; off <<= 1) {
                unsigned int u = __shfl_up_sync(0xffffffffu, v, off);
                if (lane >= off) v += u;
            }
            if (lane == 31) wsum[wrp] = v;
            __syncthreads();
            if (wrp == 0) {
                unsigned int w = wsum[lane];
                #pragma unroll
                for (int off = 1; off < 32; off <<= 1) {
                    unsigned int u = __shfl_up_sync(0xffffffffu, w, off);
                    if (lane >= off) w += u;
                }
                wsum[lane] = w;
            }
            __syncthreads();
            unsigned int incl = v + (wrp ? wsum[wrp-1] : 0u);
            unsigned int excl = incl - val;
            if (excl < need && need <= incl) { sh_d = 1023 - t; sh_sub = excl; }
            __syncthreads();
            need -= sh_sub;
            prefix |= ((unsigned long long)(unsigned int)sh_d) << shift;
            pmask  |= 1023ull << shift;
            __syncthreads();
        }
    }
    for (int i = t; i < m; i += 1024) {
        unsigned long long c = cand[i];
        if (c >= prefix) {
            int p = atomicAdd(&g_selCount[n], 1);
            g_idx[n*PPB + p] = (int)((~c) & 0x3FFFF);
        }
    }
    if (t == 0) g_done2[n] = 0;
}

// ---------------- unified MLP: gather + 3 FC (mma.sync bf16, NP-plane split) + head + scatter ----------------
template<int NP>
__global__ void __launch_bounds__(256, 1)
mma_mlp(const float* __restrict__ coarse,
        const float* __restrict__ b1, const float* __restrict__ b2, const float* __restrict__ b3,
        const float* __restrict__ wph, const float* __restrict__ bph,
        float* __restrict__ sem, int HW, int logW) {
    extern __shared__ float dynsm[];
    char* smc = (char*)dynsm;
    u32* XP = (u32*)smc;                       // NP planes of [128][72]
    u32* WP = (u32*)(smc + NP*PLB);            // NP planes of [128][72]
    const int MISC = 2*NP*PLB;
    float* bias_s  = (float*)(smc + MISC);
    float* wps     = (float*)(smc + MISC + 512);
    float* hsum    = (float*)(smc + MISC + 2096);
    float* scoarse = (float*)(smc + MISC + 3632);

    __shared__ int   sx0[128], sy0[128];
    __shared__ float sw0[128], sw1[128], sw2[128], sw3[128];

    int tid = threadIdx.x, lane = tid & 31, wrp = tid >> 5;
    int pBase = blockIdx.x * 128;
    int n = pBase >> 13;

    // zero X planes
    {
        float4 z = make_float4(0.f, 0.f, 0.f, 0.f);
        float4* xz = (float4*)smc;
        #pragma unroll
        for (int q = 0; q < NP*9; q++) xz[tid + 256*q] = z;
    }
    if (tid < 128) {
        int id = g_idx[pBase + tid];
        int W = 1 << logW;
        float inv = 1.f / (float)W;
        float px = ((float)(id & (W-1)) + 0.5f) * inv;
        float py = ((float)(id >> logW) + 0.5f) * inv;
        float fx = px * 256.f - 0.5f, fy = py * 256.f - 0.5f;
        float fx0 = floorf(fx), fy0 = floorf(fy);
        float wx1 = fx - fx0, wy1 = fy - fy0;
        sx0[tid] = (int)fx0; sy0[tid] = (int)fy0;
        sw0[tid] = (1.f-wx1)*(1.f-wy1);
        sw1[tid] = wx1*(1.f-wy1);
        sw2[tid] = (1.f-wx1)*wy1;
        sw3[tid] = wx1*wy1;
        float cx = px*128.f - 0.5f, cy = py*128.f - 0.5f;
        float cx0f = floorf(cx), cy0f = floorf(cy);
        int x0 = (int)cx0f, y0 = (int)cy0f;
        float cwx = cx - cx0f, cwy = cy - cy0f;
        #pragma unroll
        for (int cc = 0; cc < NCLS; cc++) {
            const float* p = coarse + (size_t)(n*NCLS + cc)*CH*CH;
            float acc = 0.f;
            if (x0 >= 0   && y0 >= 0  ) acc += (1.f-cwx)*(1.f-cwy)*p[y0*CH + x0];
            if (x0+1 < CH && y0 >= 0  ) acc += cwx*(1.f-cwy)*p[y0*CH + x0+1];
            if (x0 >= 0   && y0+1 < CH) acc += (1.f-cwx)*cwy*p[(y0+1)*CH + x0];
            if (x0+1 < CH && y0+1 < CH) acc += cwx*cwy*p[(y0+1)*CH + x0+1];
            scoarse[cc*128 + tid] = acc;
        }
    }
    for (int j = tid; j < 3*KIN; j += 256) wps[j] = wph[j];
    __syncthreads();

    // feature gather -> X planes (warp-per-point, lane = 4 channels = 2 pairs)
    const float* fbase = g_featT + (size_t)n*FH*FH*NIN;
    int ch0 = lane << 2;
    #pragma unroll 4
    for (int it = 0; it < 16; it++) {
        int pt = wrp + it*8;
        int x0 = sx0[pt], y0 = sy0[pt];
        bool xv0 = (x0 >= 0), xv1 = (x0+1 < FH), yv0 = (y0 >= 0), yv1 = (y0+1 < FH);
        float a0 = 0.f, a1 = 0.f, a2 = 0.f, a3 = 0.f;
        if (xv0 && yv0) { float w = sw0[pt]; float4 v = *(const float4*)(fbase + (size_t)((y0  )*FH + x0  )*NIN + ch0);
                          a0 += w*v.x; a1 += w*v.y; a2 += w*v.z; a3 += w*v.w; }
        if (xv1 && yv0) { float w = sw1[pt]; float4 v = *(const float4*)(fbase + (size_t)((y0  )*FH + x0+1)*NIN + ch0);
                          a0 += w*v.x; a1 += w*v.y; a2 += w*v.z; a3 += w*v.w; }
        if (xv0 && yv1) { float w = sw2[pt]; float4 v = *(const float4*)(fbase + (size_t)((y0+1)*FH + x0  )*NIN + ch0);
                          a0 += w*v.x; a1 += w*v.y; a2 += w*v.z; a3 += w*v.w; }
        if (xv1 && yv1) { float w = sw3[pt]; float4 v = *(const float4*)(fbase + (size_t)((y0+1)*FH + x0+1)*NIN + ch0);
                          a0 += w*v.x; a1 += w*v.y; a2 += w*v.z; a3 += w*v.w; }
        int pp = pt*KP + (lane << 1);
        float r0 = a0, r1 = a1, r2 = a2, r3 = a3;
        #pragma unroll
        for (int p = 0; p < NP; p++) {
            u32 pkA = pack_bf16x2(r0, r1);
            u32 pkB = pack_bf16x2(r2, r3);
            *(uint2*)(XP + p*PLU + pp) = make_uint2(pkA, pkB);
            r0 -= bf16lo_f(pkA); r1 -= bf16hi_f(pkA);
            r2 -= bf16lo_f(pkB); r3 -= bf16hi_f(pkB);
        }
    }
    // coarse -> pairs 64 (k128,k129), 65 (k130, 0); head coarse terms + bias -> hsum
    if (tid < 128) {
        float c0 = scoarse[tid], c1 = scoarse[128 + tid], c2 = scoarse[256 + tid];
        float r0 = c0, r1 = c1, r2 = c2, r3 = 0.f;
        #pragma unroll
        for (int p = 0; p < NP; p++) {
            u32 pkA = pack_bf16x2(r0, r1);
            u32 pkB = pack_bf16x2(r2, r3);
            *(uint2*)(XP + p*PLU + tid*KP + 64) = make_uint2(pkA, pkB);
            r0 -= bf16lo_f(pkA); r1 -= bf16hi_f(pkA);
            r2 -= bf16lo_f(pkB); r3 -= bf16hi_f(pkB);
        }
        #pragma unroll
        for (int c = 0; c < NCLS; c++)
            hsum[c*128 + tid] = wps[c*KIN + 128]*c0 + wps[c*KIN + 129]*c1 + wps[c*KIN + 130]*c2 + __ldg(&bph[c]);
    }
    __syncthreads();

    const int NPROD = (NP == 2) ? 3 : 6;
    const int PA[6] = {0, 0, 1, 1, 0, 2};
    const int PB[6] = {0, 1, 0, 1, 2, 0};

    int g = lane >> 2;
    int tig = lane & 3;
    int m0 = wrp * 16;
    int rA = (m0 + g)*KP;
    int rB = (m0 + g + 8)*KP;

    for (int l = 0; l < 3; l++) {
        // stage NP weight planes (contiguous in g_Wbf3 since planes are adjacent)
        {
            const float4* wsrc = (const float4*)(g_Wbf3 + (size_t)l*3*WPLANE);
            float4* wdst = (float4*)WP;
            #pragma unroll
            for (int q = 0; q < NP*9; q++) wdst[tid + 256*q] = wsrc[tid + 256*q];
        }
        const float* Bp = (l == 0) ? b1 : ((l == 1) ? b2 : b3);
        if (tid < 128) bias_s[tid] = __ldg(&Bp[tid]);
        __syncthreads();

        float acc[16][4];
        #pragma unroll
        for (int nt = 0; nt < 16; nt++) {
            acc[nt][0] = 0.f; acc[nt][1] = 0.f; acc[nt][2] = 0.f; acc[nt][3] = 0.f;
        }
        for (int ks = 0; ks < 9; ks++) {
            int kp = ks*8 + tig;
            u32 af[NP][4];
            #pragma unroll
            for (int p = 0; p < NP; p++) {
                const u32* Xp = XP + p*PLU;
                af[p][0] = Xp[rA + kp];     af[p][1] = Xp[rB + kp];
                af[p][2] = Xp[rA + kp + 4]; af[p][3] = Xp[rB + kp + 4];
            }
            #pragma unroll
            for (int nt = 0; nt < 16; nt++) {
                int nrow = (nt*8 + g)*KP + kp;
                u32 bfr[NP][2];
                #pragma unroll
                for (int p = 0; p < NP; p++) {
                    const u32* Wpp = WP + p*PLU;
                    bfr[p][0] = Wpp[nrow]; bfr[p][1] = Wpp[nrow + 4];
                }
                #pragma unroll
                for (int q = 0; q < NPROD; q++)
                    mma16816(acc[nt], af[PA[q]][0], af[PA[q]][1], af[PA[q]][2], af[PA[q]][3],
                             bfr[PB[q]][0], bfr[PB[q]][1]);
            }
        }
        __syncthreads();   // everyone done reading X/W before epilogue writes X

        #pragma unroll
        for (int nt = 0; nt < 16; nt++) {
            int col = nt*8 + (tig << 1);
            float bA = bias_s[col], bB = bias_s[col + 1];
            float v0 = fmaxf(acc[nt][0] + bA, 0.f);
            float v1 = fmaxf(acc[nt][1] + bB, 0.f);
            float v2 = fmaxf(acc[nt][2] + bA, 0.f);
            float v3 = fmaxf(acc[nt][3] + bB, 0.f);
            int idx = nt*4 + tig;
            float r0 = v0, r1 = v1, r2 = v2, r3 = v3;
            #pragma unroll
            for (int p = 0; p < NP; p++) {
                u32 pkA = pack_bf16x2(r0, r1);
                u32 pkB = pack_bf16x2(r2, r3);
                XP[p*PLU + rA + idx] = pkA;
                XP[p*PLU + rB + idx] = pkB;
                r0 -= bf16lo_f(pkA); r1 -= bf16hi_f(pkA);
                r2 -= bf16lo_f(pkB); r3 -= bf16hi_f(pkB);
            }
        }
        __syncthreads();
    }

    // head: per-thread point, reconstruct x = sum of planes
    if (tid < 128) {
        float s0 = 0.f, s1 = 0.f, s2 = 0.f;
        #pragma unroll 8
        for (int kp = 0; kp < 64; kp++) {
            float x0 = 0.f, x1 = 0.f;
            #pragma unroll
            for (int p = 0; p < NP; p++) {
                u32 v = XP[p*PLU + tid*KP + kp];
                x0 += bf16lo_f(v); x1 += bf16hi_f(v);
            }
            int k = kp << 1;
            s0 += wps[k]*x0 + wps[k+1]*x1;
            s1 += wps[KIN + k]*x0 + wps[KIN + k + 1]*x1;
            s2 += wps[2*KIN + k]*x0 + wps[2*KIN + k + 1]*x1;
        }
        int id = g_idx[pBase + tid];
        sem[(size_t)(n*NCLS + 0)*HW + id] = hsum[tid] + s0;
        sem[(size_t)(n*NCLS + 1)*HW + id] = hsum[128 + tid] + s1;
        sem[(size_t)(n*NCLS + 2)*HW + id] = hsum[256 + tid] + s2;
    }
}

// ---------------- launch ----------------
extern "C" void kernel_launch(void* const* d_in, const int* in_sizes, int n_in,
                              void* d_out, int out_size) {
    const float* coarse = (const float*)d_in[0];
    const float* feat   = (const float*)d_in[1];
    const float* w1 = (const float*)d_in[2];
    const float* b1 = (const float*)d_in[3];
    const float* w2 = (const float*)d_in[4];
    const float* b2 = (const float*)d_in[5];
    const float* w3 = (const float*)d_in[6];
    const float* b3 = (const float*)d_in[7];
    const float* wp = (const float*)d_in[8];
    const float* bp = (const float*)d_in[9];
    float* out = (float*)d_out;

    float* sem256;
    cudaGetSymbolAddress((void**)&sem256, g_sem256);

    static cudaStream_t sSide = nullptr;
    static cudaEvent_t evFork = nullptr, evJoin = nullptr;
    if (sSide == nullptr) {
        cudaStreamCreateWithFlags(&sSide, cudaStreamNonBlocking);
        cudaEventCreateWithFlags(&evFork, cudaEventDisableTiming);
        cudaEventCreateWithFlags(&evJoin, cudaEventDisableTiming);
    }

    const int SM3 = 2*3*PLB + 5200;   // 226,384 B
    const int SM2 = 2*2*PLB + 5200;   // 152,656 B
    cudaFuncSetAttribute(mma_mlp<3>, cudaFuncAttributeMaxDynamicSharedMemorySize, SM3);
    cudaFuncSetAttribute(mma_mlp<2>, cudaFuncAttributeMaxDynamicSharedMemorySize, SM2);

    cudaEventRecord(evFork, 0);
    cudaStreamWaitEvent(sSide, evFork, 0);
    transpose_kernel<<<dim3(2048, 4, 4), dim3(32, 8), 0, sSide>>>(feat);
    cudaEventRecord(evJoin, sSide);

    prep_kernel<<<256, 256>>>(w1, w2, w3);

    for (int step = 0; step < 2; step++) {
        int logW = (step == 0) ? 8 : 9;
        int HW   = 1 << (2*logW);
        const float* semIn = (step == 0) ? coarse : sem256;
        float* semOut      = (step == 0) ? sem256 : out;

        upsample_sel<<<dim3(HW/1024, NB), 256>>>(semIn, semOut, logW);
        compact_sel<<<dim3(HW/4096, NB), 1024>>>(HW);

        if (step == 0) {
            cudaStreamWaitEvent(0, evJoin, 0);
            mma_mlp<3><<<PTOT/128, 256, SM3>>>(coarse, b1, b2, b3, wp, bp, semOut, HW, logW);
        } else {
            mma_mlp<2><<<PTOT/128, 256, SM2>>>(coarse, b1, b2, b3, wp, bp, semOut, HW, logW);
        }
    }
}

// round 12
// speedup vs baseline: 1.1838x; 1.0420x over previous
#include <cuda_runtime.h>
#include <math.h>

typedef unsigned int       u32;
typedef unsigned long long u64;
typedef unsigned short     u16;

#define NB   4
#define NCLS 3
#define FH   256
#define CH   128
#define NIN  128
#define KIN  131
#define PPB  8192
#define PTOT 32768
#define KEYSTRIDE 262144
#define TOPK 8192u

#define PLU    9216               // u32 per plane: 9 ksteps * 16 nt * 32 lanes * 2 (W) == 8 wrp * 9 ks * 32 * 4 (X)
#define PLB    36864              // bytes per plane

// ---------------- scratch ----------------
__device__ float        g_featT[(size_t)NB*FH*FH*NIN];
__device__ float        g_sem256[NB*NCLS*256*256];
__device__ unsigned int g_keys[NB*KEYSTRIDE];
__device__ unsigned int g_hist2[NB*4096];
__device__ unsigned long long g_cand[(size_t)NB*KEYSTRIDE];
__device__ int          g_bstar[NB];
__device__ int          g_kRem[NB];
__device__ int          g_selCount[NB];
__device__ int          g_candCount[NB];
__device__ int          g_done1[NB];
__device__ int          g_done2[NB];
__device__ int          g_idx[PTOT];
__device__ __align__(16) u32 g_Wf[3*3*PLU];   // [layer][plane][fragment-major]

__device__ __forceinline__ unsigned int fkey(float f) {
    unsigned int u = __float_as_uint(f);
    return (u & 0x80000000u) ? ~u : (u | 0x80000000u);
}
__device__ __forceinline__ u32 pack_bf16x2(float lo_val, float hi_val) {
    u32 r;
    asm("cvt.rn.bf16x2.f32 %0, %1, %2;" : "=r"(r) : "f"(hi_val), "f"(lo_val));
    return r;
}
__device__ __forceinline__ float bf16lo_f(u32 p) { return __uint_as_float(p << 16); }
__device__ __forceinline__ float bf16hi_f(u32 p) { return __uint_as_float(p & 0xFFFF0000u); }

__device__ __forceinline__ void mma16816(float* d, u32 a0, u32 a1, u32 a2, u32 a3, u32 b0, u32 b1) {
    asm volatile("mma.sync.aligned.m16n8k16.row.col.f32.bf16.bf16.f32 {%0,%1,%2,%3}, {%4,%5,%6,%7}, {%8,%9}, {%0,%1,%2,%3};" : "+f"(d[0]), "+f"(d[1]), "+f"(d[2]), "+f"(d[3]) : "r"(a0), "r"(a1), "r"(a2), "r"(a3), "r"(b0), "r"(b1));
}

// X fragment-major address (u32 units) for block-point pt (0..127), k-pair pi (0..71)
__device__ __forceinline__ int xf_addr(int pt, int pi) {
    int w = pt >> 4, r = pt & 15;
    int g = r & 7, rh = r >> 3;
    int ks = pi >> 3, sub = pi & 7;
    int tg = sub & 3, kh = sub >> 2;
    return (((w*9 + ks)*32 + (g << 2) + tg) << 2) + rh + (kh << 1);
}

// ---------------- one-time prep: hist zero + fragment-major 3-plane W pack ----------------
__global__ void prep_kernel(const float* __restrict__ w1, const float* __restrict__ w2,
                            const float* __restrict__ w3) {
    int i = blockIdx.x*blockDim.x + threadIdx.x;
    int stride = gridDim.x*blockDim.x;
    for (int j = i; j < NB*4096; j += stride) g_hist2[j] = 0;
    if (i < NB) { g_done1[i] = 0; g_done2[i] = 0; g_selCount[i] = 0; g_candCount[i] = 0; }
    // e = ((ks*16+nt)*32 + lane)*2 + reg ; n = nt*8 + lane/4 ; k0 = ks*16 + (lane&3)*2 + reg*8
    for (int j = i; j < 3*PLU; j += stride) {
        int l = j / PLU; int e = j - l*PLU;
        int reg = e & 1;
        int lane = (e >> 1) & 31;
        int nt = (e >> 6) & 15;
        int ks = e >> 10;
        int n  = nt*8 + (lane >> 2);
        int k0 = ks*16 + (lane & 3)*2 + (reg << 3);
        const float* w = (l == 0) ? w1 : ((l == 1) ? w2 : w3);
        float v0 = (k0     < KIN) ? w[n*KIN + k0]     : 0.f;
        float v1 = (k0 + 1 < KIN) ? w[n*KIN + k0 + 1] : 0.f;
        #pragma unroll
        for (int p = 0; p < 3; p++) {
            u32 pk = pack_bf16x2(v0, v1);
            g_Wf[(l*3 + p)*PLU + e] = pk;
            v0 -= bf16lo_f(pk); v1 -= bf16hi_f(pk);
        }
    }
}

// ---------------- features NCHW -> NHWC ----------------
__global__ void transpose_kernel(const float* __restrict__ f) {
    __shared__ float tile[32][33];
    int n = blockIdx.z;
    int pix0 = blockIdx.x * 32;
    int c0   = blockIdx.y * 32;
    int tx = threadIdx.x, ty = threadIdx.y;
    #pragma unroll
    for (int i = ty; i < 32; i += 8)
        tile[i][tx] = f[(size_t)(n*NIN + c0 + i)*(FH*FH) + pix0 + tx];
    __syncthreads();
    #pragma unroll
    for (int i = ty; i < 32; i += 8)
        g_featT[(size_t)(n*(FH*FH) + pix0 + i)*NIN + c0 + tx] = tile[tx][i];
}

// ---------------- K1: upsample + keys + hist; last block resolves ----------------
__global__ void upsample_sel(const float* __restrict__ in, float* __restrict__ out, int logW) {
    __shared__ unsigned int sh[4096];
    __shared__ unsigned int wsum[8];
    __shared__ int sh_last;
    int n = blockIdx.y;
    int t = threadIdx.x;
    for (int i = t; i < 4096; i += 256) sh[i] = 0;
    __syncthreads();
    int W = 1 << logW, Hin = W >> 1;
    int HW = W << logW;
    for (int pix = blockIdx.x*256 + t; pix < HW; pix += gridDim.x*256) {
        int y = pix >> logW;  int x = pix & (W - 1);
        int y0 = (y - 1) >> 1, x0 = (x - 1) >> 1;
        float wy1 = (y & 1) ? 0.25f : 0.75f;
        float wx1 = (x & 1) ? 0.25f : 0.75f;
        int y1 = y0 + 1, x1 = x0 + 1;
        int xa = (x0 < 0) ? 0 : x0;
        int xb = (x1 > Hin-1) ? Hin-1 : x1;
        float v[NCLS];
        #pragma unroll
        for (int c = 0; c < NCLS; c++) {
            const float* p = in + (size_t)(n*NCLS + c)*Hin*Hin;
            float colA, colB;
            if (y0 < 0)            { colA = p[xa];               colB = p[xb]; }
            else if (y1 > Hin - 1) { colA = p[(Hin-1)*Hin + xa]; colB = p[(Hin-1)*Hin + xb]; }
            else {
                colA = (1.f - wy1)*p[y0*Hin + xa] + wy1*p[y1*Hin + xa];
                colB = (1.f - wy1)*p[y0*Hin + xb] + wy1*p[y1*Hin + xb];
            }
            float vv;
            if (x0 < 0)            vv = colA;
            else if (x1 > Hin - 1) vv = colB;
            else                   vv = (1.f - wx1)*colA + wx1*colB;
            v[c] = vv;
            out[(size_t)(n*NCLS + c)*HW + pix] = vv;
        }
        float hi = fmaxf(v[0], v[1]), lo = fminf(v[0], v[1]);
        float m1 = fmaxf(hi, v[2]);
        float m2 = fmaxf(lo, fminf(hi, v[2]));
        unsigned int key = fkey(m2 - m1);
        g_keys[n*KEYSTRIDE + pix] = key;
        atomicAdd(&sh[key >> 20], 1u);
    }
    __syncthreads();
    for (int i = t; i < 4096; i += 256) {
        unsigned int v = sh[i];
        if (v) atomicAdd(&g_hist2[n*4096 + i], v);
    }
    __threadfence();
    if (t == 0) {
        int old = atomicAdd(&g_done1[n], 1);
        sh_last = (old == (int)gridDim.x - 1);
    }
    __syncthreads();
    if (!sh_last) return;
    unsigned int* gh = g_hist2 + n*4096;
    int lane = t & 31, wrp = t >> 5;
    int base = 4095 - (t << 4);
    unsigned int h[16];
    unsigned int sum = 0;
    #pragma unroll
    for (int j = 0; j < 16; j++) { h[j] = gh[base - j]; sum += h[j]; }
    unsigned int v = sum;
    #pragma unroll
    for (int off = 1; off < 32; off <<= 1) {
        unsigned int u = __shfl_up_sync(0xffffffffu, v, off);
        if (lane >= off) v += u;
    }
    if (lane == 31) wsum[wrp] = v;
    __syncthreads();
    if (wrp == 0 && lane < 8) {
        unsigned int w = wsum[lane];
        #pragma unroll
        for (int off = 1; off < 8; off <<= 1) {
            unsigned int u = __shfl_up_sync(0xffu, w, off);
            if (lane >= off) w += u;
        }
        wsum[lane] = w;
    }
    __syncthreads();
    unsigned int incl = v + (wrp ? wsum[wrp-1] : 0u);
    unsigned int excl = incl - sum;
    if (excl < TOPK && TOPK <= incl) {
        unsigned int c = excl;
        #pragma unroll
        for (int j = 0; j < 16; j++) {
            if (c + h[j] >= TOPK) { g_bstar[n] = base - j; g_kRem[n] = (int)(TOPK - c); break; }
            c += h[j];
        }
    }
    #pragma unroll
    for (int j = 0; j < 16; j++) gh[base - j] = 0;
    if (t == 0) { g_selCount[n] = 0; g_candCount[n] = 0; g_done1[n] = 0; }
}

// ---------------- K2: compact (warp-aggregated) + exact candidate radix select ----------------
__global__ void __launch_bounds__(1024)
compact_sel(int HW) {
    __shared__ unsigned int hist[1024];
    __shared__ unsigned int wsum[32];
    __shared__ int sh_d, sh_last;
    __shared__ unsigned int sh_sub;
    int n = blockIdx.y;
    int t = threadIdx.x;
    int lane = t & 31, wrp = t >> 5;
    int bstar = g_bstar[n];
    const unsigned int* keys = g_keys + n*KEYSTRIDE;
    unsigned long long* cand = g_cand + (size_t)n*KEYSTRIDE;
    for (int i = blockIdx.x*1024 + t; i < HW; i += gridDim.x*1024) {
        unsigned int key = keys[i];
        int b = (int)(key >> 20);
        bool isSel  = (b > bstar);
        bool isCand = (b == bstar);
        u32 mS = __ballot_sync(0xffffffffu, isSel);
        u32 mC = __ballot_sync(0xffffffffu, isCand);
        if (isSel) {
            int ldr = __ffs(mS) - 1;
            int base;
            if (lane == ldr) base = atomicAdd(&g_selCount[n], __popc(mS));
            base = __shfl_sync(mS, base, ldr);
            g_idx[n*PPB + base + __popc(mS & ((1u << lane) - 1u))] = i;
        }
        if (isCand) {
            int ldr = __ffs(mC) - 1;
            int base;
            if (lane == ldr) base = atomicAdd(&g_candCount[n], __popc(mC));
            base = __shfl_sync(mC, base, ldr);
            cand[base + __popc(mC & ((1u << lane) - 1u))] =
                (((unsigned long long)(key & 0xFFFFFu)) << 18) | (unsigned int)((~i) & 0x3FFFF);
        }
    }
    __threadfence();
    if (t == 0) {
        int old = atomicAdd(&g_done2[n], 1);
        sh_last = (old == (int)gridDim.x - 1);
    }
    __syncthreads();
    if (!sh_last) return;
    int m = g_candCount[n];
    unsigned int need = (unsigned int)g_kRem[n];
    unsigned long long prefix = 0, pmask = 0;
    if (m > (int)need) {
        #pragma unroll
        for (int pass = 0; pass < 4; pass++) {
            int shift = 30 - 10*pass;
            hist[t] = 0;
            __syncthreads();
            for (int i = t; i < m; i += 1024) {
                unsigned long long c = cand[i];
                if ((c & pmask) == prefix)
                    atomicAdd(&hist[(unsigned int)(c >> shift) & 1023u], 1u);
            }
            __syncthreads();
            unsigned int val = hist[1023 - t];
            unsigned int v = val;
            #pragma unroll
            for (int off = 1; off < 32; off <<= 1) {
                unsigned int u = __shfl_up_sync(0xffffffffu, v, off);
                if (lane >= off) v += u;
            }
            if (lane == 31) wsum[wrp] = v;
            __syncthreads();
            if (wrp == 0) {
                unsigned int w = wsum[lane];
                #pragma unroll
                for (int off = 1; off < 32; off <<= 1) {
                    unsigned int u = __shfl_up_sync(0xffffffffu, w, off);
                    if (lane >= off) w += u;
                }
                wsum[lane] = w;
            }
            __syncthreads();
            unsigned int incl = v + (wrp ? wsum[wrp-1] : 0u);
            unsigned int excl = incl - val;
            if (excl < need && need <= incl) { sh_d = 1023 - t; sh_sub = excl; }
            __syncthreads();
            need -= sh_sub;
            prefix |= ((unsigned long long)(unsigned int)sh_d) << shift;
            pmask  |= 1023ull << shift;
            __syncthreads();
        }
    }
    for (int i = t; i < m; i += 1024) {
        unsigned long long c = cand[i];
        if (c >= prefix) {
            int p = atomicAdd(&g_selCount[n], 1);
            g_idx[n*PPB + p] = (int)((~c) & 0x3FFFF);
        }
    }
    if (t == 0) g_done2[n] = 0;
}

// ---------------- unified MLP: fragment-major operands, mma.sync bf16, NP-plane split ----------------
template<int NP>
__global__ void __launch_bounds__(256, 1)
mma_mlp(const float* __restrict__ coarse,
        const float* __restrict__ b1, const float* __restrict__ b2, const float* __restrict__ b3,
        const float* __restrict__ wph, const float* __restrict__ bph,
        float* __restrict__ sem, int HW, int logW) {
    extern __shared__ float dynsm[];
    char* smc = (char*)dynsm;
    u32* XP = (u32*)smc;                       // NP planes, fragment-major
    u32* WP = (u32*)(smc + NP*PLB);            // NP planes, fragment-major
    const int MISC = 2*NP*PLB;
    float* bias_s  = (float*)(smc + MISC);
    float* wps     = (float*)(smc + MISC + 512);
    float* hsum    = (float*)(smc + MISC + 2096);
    float* scoarse = (float*)(smc + MISC + 3632);

    __shared__ int   sx0[128], sy0[128];
    __shared__ float sw0[128], sw1[128], sw2[128], sw3[128];

    int tid = threadIdx.x, lane = tid & 31, wrp = tid >> 5;
    int pBase = blockIdx.x * 128;
    int n = pBase >> 13;

    // zero X planes
    {
        float4 z = make_float4(0.f, 0.f, 0.f, 0.f);
        float4* xz = (float4*)smc;
        #pragma unroll
        for (int q = 0; q < NP*9; q++) xz[tid + 256*q] = z;
    }
    if (tid < 128) {
        int id = g_idx[pBase + tid];
        int W = 1 << logW;
        float inv = 1.f / (float)W;
        float px = ((float)(id & (W-1)) + 0.5f) * inv;
        float py = ((float)(id >> logW) + 0.5f) * inv;
        float fx = px * 256.f - 0.5f, fy = py * 256.f - 0.5f;
        float fx0 = floorf(fx), fy0 = floorf(fy);
        float wx1 = fx - fx0, wy1 = fy - fy0;
        sx0[tid] = (int)fx0; sy0[tid] = (int)fy0;
        sw0[tid] = (1.f-wx1)*(1.f-wy1);
        sw1[tid] = wx1*(1.f-wy1);
        sw2[tid] = (1.f-wx1)*wy1;
        sw3[tid] = wx1*wy1;
        float cx = px*128.f - 0.5f, cy = py*128.f - 0.5f;
        float cx0f = floorf(cx), cy0f = floorf(cy);
        int x0 = (int)cx0f, y0 = (int)cy0f;
        float cwx = cx - cx0f, cwy = cy - cy0f;
        #pragma unroll
        for (int cc = 0; cc < NCLS; cc++) {
            const float* p = coarse + (size_t)(n*NCLS + cc)*CH*CH;
            float acc = 0.f;
            if (x0 >= 0   && y0 >= 0  ) acc += (1.f-cwx)*(1.f-cwy)*p[y0*CH + x0];
            if (x0+1 < CH && y0 >= 0  ) acc += cwx*(1.f-cwy)*p[y0*CH + x0+1];
            if (x0 >= 0   && y0+1 < CH) acc += (1.f-cwx)*cwy*p[(y0+1)*CH + x0];
            if (x0+1 < CH && y0+1 < CH) acc += cwx*cwy*p[(y0+1)*CH + x0+1];
            scoarse[cc*128 + tid] = acc;
        }
    }
    for (int j = tid; j < 3*KIN; j += 256) wps[j] = wph[j];
    __syncthreads();

    // feature gather -> X fragment-major planes (warp-per-point, lane = 4 channels = pairs 2*lane, 2*lane+1)
    const float* fbase = g_featT + (size_t)n*FH*FH*NIN;
    int ch0 = lane << 2;
    #pragma unroll 4
    for (int it = 0; it < 16; it++) {
        int pt = wrp + it*8;
        int x0 = sx0[pt], y0 = sy0[pt];
        bool xv0 = (x0 >= 0), xv1 = (x0+1 < FH), yv0 = (y0 >= 0), yv1 = (y0+1 < FH);
        float a0 = 0.f, a1 = 0.f, a2 = 0.f, a3 = 0.f;
        if (xv0 && yv0) { float w = sw0[pt]; float4 v = *(const float4*)(fbase + (size_t)((y0  )*FH + x0  )*NIN + ch0);
                          a0 += w*v.x; a1 += w*v.y; a2 += w*v.z; a3 += w*v.w; }
        if (xv1 && yv0) { float w = sw1[pt]; float4 v = *(const float4*)(fbase + (size_t)((y0  )*FH + x0+1)*NIN + ch0);
                          a0 += w*v.x; a1 += w*v.y; a2 += w*v.z; a3 += w*v.w; }
        if (xv0 && yv1) { float w = sw2[pt]; float4 v = *(const float4*)(fbase + (size_t)((y0+1)*FH + x0  )*NIN + ch0);
                          a0 += w*v.x; a1 += w*v.y; a2 += w*v.z; a3 += w*v.w; }
        if (xv1 && yv1) { float w = sw3[pt]; float4 v = *(const float4*)(fbase + (size_t)((y0+1)*FH + x0+1)*NIN + ch0);
                          a0 += w*v.x; a1 += w*v.y; a2 += w*v.z; a3 += w*v.w; }
        int ad0 = xf_addr(pt, (lane << 1));
        int ad1 = xf_addr(pt, (lane << 1) + 1);
        float r0 = a0, r1 = a1, r2 = a2, r3 = a3;
        #pragma unroll
        for (int p = 0; p < NP; p++) {
            u32 pkA = pack_bf16x2(r0, r1);
            u32 pkB = pack_bf16x2(r2, r3);
            XP[p*PLU + ad0] = pkA;
            XP[p*PLU + ad1] = pkB;
            r0 -= bf16lo_f(pkA); r1 -= bf16hi_f(pkA);
            r2 -= bf16lo_f(pkB); r3 -= bf16hi_f(pkB);
        }
    }
    // coarse -> pairs 64 (k128,k129), 65 (k130, 0); head coarse terms + bias -> hsum
    if (tid < 128) {
        float c0 = scoarse[tid], c1 = scoarse[128 + tid], c2 = scoarse[256 + tid];
        int ad64 = xf_addr(tid, 64);
        int ad65 = xf_addr(tid, 65);
        float r0 = c0, r1 = c1, r2 = c2, r3 = 0.f;
        #pragma unroll
        for (int p = 0; p < NP; p++) {
            u32 pkA = pack_bf16x2(r0, r1);
            u32 pkB = pack_bf16x2(r2, r3);
            XP[p*PLU + ad64] = pkA;
            XP[p*PLU + ad65] = pkB;
            r0 -= bf16lo_f(pkA); r1 -= bf16hi_f(pkA);
            r2 -= bf16lo_f(pkB); r3 -= bf16hi_f(pkB);
        }
        #pragma unroll
        for (int c = 0; c < NCLS; c++)
            hsum[c*128 + tid] = wps[c*KIN + 128]*c0 + wps[c*KIN + 129]*c1 + wps[c*KIN + 130]*c2 + __ldg(&bph[c]);
    }
    __syncthreads();

    const int NPROD = (NP == 2) ? 3 : 6;
    const int PA[6] = {0, 0, 1, 1, 0, 2};
    const int PB[6] = {0, 1, 0, 1, 2, 0};

    int g = lane >> 2;
    int tig = lane & 3;

    for (int l = 0; l < 3; l++) {
        // stage NP weight planes (fragment-major; plain contiguous copy)
        {
            const float4* wsrc = (const float4*)(g_Wf + (size_t)l*3*PLU);
            float4* wdst = (float4*)WP;
            #pragma unroll
            for (int q = 0; q < NP*9; q++) wdst[tid + 256*q] = wsrc[tid + 256*q];
        }
        const float* Bp = (l == 0) ? b1 : ((l == 1) ? b2 : b3);
        if (tid < 128) bias_s[tid] = __ldg(&Bp[tid]);
        __syncthreads();

        float acc[16][4];
        #pragma unroll
        for (int nt = 0; nt < 16; nt++) {
            acc[nt][0] = 0.f; acc[nt][1] = 0.f; acc[nt][2] = 0.f; acc[nt][3] = 0.f;
        }
        for (int ks = 0; ks < 9; ks++) {
            uint4 af[NP];
            #pragma unroll
            for (int p = 0; p < NP; p++)
                af[p] = *(const uint4*)(XP + p*PLU + (((wrp*9 + ks)*32 + lane) << 2));
            #pragma unroll
            for (int nt = 0; nt < 16; nt++) {
                int boff = (((ks*16 + nt)*32 + lane) << 1);
                uint2 bfr[NP];
                #pragma unroll
                for (int p = 0; p < NP; p++)
                    bfr[p] = *(const uint2*)(WP + p*PLU + boff);
                #pragma unroll
                for (int q = 0; q < NPROD; q++)
                    mma16816(acc[nt], af[PA[q]].x, af[PA[q]].y, af[PA[q]].z, af[PA[q]].w,
                             bfr[PB[q]].x, bfr[PB[q]].y);
            }
        }
        __syncthreads();   // everyone done reading X/W before epilogue writes X

        #pragma unroll
        for (int nt = 0; nt < 16; nt++) {
            int col = nt*8 + (tig << 1);
            float bA = bias_s[col], bB = bias_s[col + 1];
            float v0 = fmaxf(acc[nt][0] + bA, 0.f);
            float v1 = fmaxf(acc[nt][1] + bB, 0.f);
            float v2 = fmaxf(acc[nt][2] + bA, 0.f);
            float v3 = fmaxf(acc[nt][3] + bB, 0.f);
            int pi = nt*4 + tig;
            int adA = xf_addr(wrp*16 + g, pi);        // slot kh*2   (row g)
            float r0 = v0, r1 = v1, r2 = v2, r3 = v3;
            #pragma unroll
            for (int p = 0; p < NP; p++) {
                u32 pkA = pack_bf16x2(r0, r1);        // row g
                u32 pkB = pack_bf16x2(r2, r3);        // row g+8 -> adjacent slot
                *(uint2*)(XP + p*PLU + adA) = make_uint2(pkA, pkB);
                r0 -= bf16lo_f(pkA); r1 -= bf16hi_f(pkA);
                r2 -= bf16lo_f(pkB); r3 -= bf16hi_f(pkB);
            }
        }
        __syncthreads();
    }

    // head: per-thread point, reconstruct x = sum of planes (fragment addressing)
    if (tid < 128) {
        float s0 = 0.f, s1 = 0.f, s2 = 0.f;
        #pragma unroll 8
        for (int kp = 0; kp < 64; kp++) {
            int ad = xf_addr(tid, kp);
            float x0 = 0.f, x1 = 0.f;
            #pragma unroll
            for (int p = 0; p < NP; p++) {
                u32 v = XP[p*PLU + ad];
                x0 += bf16lo_f(v); x1 += bf16hi_f(v);
            }
            int k = kp << 1;
            s0 += wps[k]*x0 + wps[k+1]*x1;
            s1 += wps[KIN + k]*x0 + wps[KIN + k + 1]*x1;
            s2 += wps[2*KIN + k]*x0 + wps[2*KIN + k + 1]*x1;
        }
        int id = g_idx[pBase + tid];
        sem[(size_t)(n*NCLS + 0)*HW + id] = hsum[tid] + s0;
        sem[(size_t)(n*NCLS + 1)*HW + id] = hsum[128 + tid] + s1;
        sem[(size_t)(n*NCLS + 2)*HW + id] = hsum[256 + tid] + s2;
    }
}

// ---------------- launch ----------------
extern "C" void kernel_launch(void* const* d_in, const int* in_sizes, int n_in,
                              void* d_out, int out_size) {
    const float* coarse = (const float*)d_in[0];
    const float* feat   = (const float*)d_in[1];
    const float* w1 = (const float*)d_in[2];
    const float* b1 = (const float*)d_in[3];
    const float* w2 = (const float*)d_in[4];
    const float* b2 = (const float*)d_in[5];
    const float* w3 = (const float*)d_in[6];
    const float* b3 = (const float*)d_in[7];
    const float* wp = (const float*)d_in[8];
    const float* bp = (const float*)d_in[9];
    float* out = (float*)d_out;

    float* sem256;
    cudaGetSymbolAddress((void**)&sem256, g_sem256);

    static cudaStream_t sSide = nullptr;
    static cudaEvent_t evFork = nullptr, evJoin = nullptr;
    if (sSide == nullptr) {
        cudaStreamCreateWithFlags(&sSide, cudaStreamNonBlocking);
        cudaEventCreateWithFlags(&evFork, cudaEventDisableTiming);
        cudaEventCreateWithFlags(&evJoin, cudaEventDisableTiming);
    }

    const int SM3 = 2*3*PLB + 5200;   // 226,384 B
    const int SM2 = 2*2*PLB + 5200;   // 152,656 B
    cudaFuncSetAttribute(mma_mlp<3>, cudaFuncAttributeMaxDynamicSharedMemorySize, SM3);
    cudaFuncSetAttribute(mma_mlp<2>, cudaFuncAttributeMaxDynamicSharedMemorySize, SM2);

    cudaEventRecord(evFork, 0);
    cudaStreamWaitEvent(sSide, evFork, 0);
    transpose_kernel<<<dim3(2048, 4, 4), dim3(32, 8), 0, sSide>>>(feat);
    cudaEventRecord(evJoin, sSide);

    prep_kernel<<<256, 256>>>(w1, w2, w3);

    for (int step = 0; step < 2; step++) {
        int logW = (step == 0) ? 8 : 9;
        int HW   = 1 << (2*logW);
        const float* semIn = (step == 0) ? coarse : sem256;
        float* semOut      = (step == 0) ? sem256 : out;

        upsample_sel<<<dim3(HW/1024, NB), 256>>>(semIn, semOut, logW);
        compact_sel<<<dim3(HW/4096, NB), 1024>>>(HW);

        if (step == 0) {
            cudaStreamWaitEvent(0, evJoin, 0);
            mma_mlp<3><<<PTOT/128, 256, SM3>>>(coarse, b1, b2, b3, wp, bp, semOut, HW, logW);
        } else {
            mma_mlp<2><<<PTOT/128, 256, SM2>>>(coarse, b1, b2, b3, wp, bp, semOut, HW, logW);
        }
    }
}

// round 13
// speedup vs baseline: 1.1963x; 1.0105x over previous
#include <cuda_runtime.h>
#include <math.h>

typedef unsigned int       u32;
typedef unsigned long long u64;
typedef unsigned short     u16;

#define NB   4
#define NCLS 3
#define FH   256
#define CH   128
#define NIN  128
#define KIN  131
#define PPB  8192
#define PTOT 32768
#define KEYSTRIDE 262144
#define TOPK 8192u

#define PLU    9216               // u32 per plane
#define PLB    36864              // bytes per plane
#define C3CAP  2048

// ---------------- scratch ----------------
__device__ float        g_featT[(size_t)NB*FH*FH*NIN];
__device__ float        g_sem256[NB*NCLS*256*256];
__device__ unsigned int g_keys[NB*KEYSTRIDE];
__device__ unsigned int g_hist2[NB*4096];
__device__ unsigned int g_h2[NB*1024];
__device__ unsigned long long g_cand[(size_t)NB*KEYSTRIDE];
__device__ int          g_bstar[NB];
__device__ int          g_kRem[NB];
__device__ int          g_selCount[NB];
__device__ int          g_candCount[NB];
__device__ int          g_done1[NB];
__device__ int          g_done2[NB];
__device__ int          g_idx[PTOT];
__device__ __align__(16) u32 g_Wf[3*3*PLU];   // [layer][plane][fragment-major]

__device__ __forceinline__ unsigned int fkey(float f) {
    unsigned int u = __float_as_uint(f);
    return (u & 0x80000000u) ? ~u : (u | 0x80000000u);
}
__device__ __forceinline__ u32 pack_bf16x2(float lo_val, float hi_val) {
    u32 r;
    asm("cvt.rn.bf16x2.f32 %0, %1, %2;" : "=r"(r) : "f"(hi_val), "f"(lo_val));
    return r;
}
__device__ __forceinline__ float bf16lo_f(u32 p) { return __uint_as_float(p << 16); }
__device__ __forceinline__ float bf16hi_f(u32 p) { return __uint_as_float(p & 0xFFFF0000u); }

__device__ __forceinline__ void mma16816(float* d, u32 a0, u32 a1, u32 a2, u32 a3, u32 b0, u32 b1) {
    asm volatile("mma.sync.aligned.m16n8k16.row.col.f32.bf16.bf16.f32 {%0,%1,%2,%3}, {%4,%5,%6,%7}, {%8,%9}, {%0,%1,%2,%3};" : "+f"(d[0]), "+f"(d[1]), "+f"(d[2]), "+f"(d[3]) : "r"(a0), "r"(a1), "r"(a2), "r"(a3), "r"(b0), "r"(b1));
}

// X fragment-major address (u32 units) for block-point pt (0..127), k-pair pi (0..71)
__device__ __forceinline__ int xf_addr(int pt, int pi) {
    int w = pt >> 4, r = pt & 15;
    int g = r & 7, rh = r >> 3;
    int ks = pi >> 3, sub = pi & 7;
    int tg = sub & 3, kh = sub >> 2;
    return (((w*9 + ks)*32 + (g << 2) + tg) << 2) + rh + (kh << 1);
}

// ---------------- one-time prep: hist zero + fragment-major 3-plane W pack ----------------
__global__ void prep_kernel(const float* __restrict__ w1, const float* __restrict__ w2,
                            const float* __restrict__ w3) {
    int i = blockIdx.x*blockDim.x + threadIdx.x;
    int stride = gridDim.x*blockDim.x;
    for (int j = i; j < NB*4096; j += stride) g_hist2[j] = 0;
    for (int j = i; j < NB*1024; j += stride) g_h2[j] = 0;
    if (i < NB) { g_done1[i] = 0; g_done2[i] = 0; g_selCount[i] = 0; g_candCount[i] = 0; }
    for (int j = i; j < 3*PLU; j += stride) {
        int l = j / PLU; int e = j - l*PLU;
        int reg = e & 1;
        int lane = (e >> 1) & 31;
        int nt = (e >> 6) & 15;
        int ks = e >> 10;
        int n  = nt*8 + (lane >> 2);
        int k0 = ks*16 + (lane & 3)*2 + (reg << 3);
        const float* w = (l == 0) ? w1 : ((l == 1) ? w2 : w3);
        float v0 = (k0     < KIN) ? w[n*KIN + k0]     : 0.f;
        float v1 = (k0 + 1 < KIN) ? w[n*KIN + k0 + 1] : 0.f;
        #pragma unroll
        for (int p = 0; p < 3; p++) {
            u32 pk = pack_bf16x2(v0, v1);
            g_Wf[(l*3 + p)*PLU + e] = pk;
            v0 -= bf16lo_f(pk); v1 -= bf16hi_f(pk);
        }
    }
}

// ---------------- features NCHW -> NHWC ----------------
__global__ void transpose_kernel(const float* __restrict__ f) {
    __shared__ float tile[32][33];
    int n = blockIdx.z;
    int pix0 = blockIdx.x * 32;
    int c0   = blockIdx.y * 32;
    int tx = threadIdx.x, ty = threadIdx.y;
    #pragma unroll
    for (int i = ty; i < 32; i += 8)
        tile[i][tx] = f[(size_t)(n*NIN + c0 + i)*(FH*FH) + pix0 + tx];
    __syncthreads();
    #pragma unroll
    for (int i = ty; i < 32; i += 8)
        g_featT[(size_t)(n*(FH*FH) + pix0 + i)*NIN + c0 + tx] = tile[tx][i];
}

// ---------------- K1: upsample + keys + hist; last block resolves ----------------
__global__ void upsample_sel(const float* __restrict__ in, float* __restrict__ out, int logW) {
    __shared__ unsigned int sh[4096];
    __shared__ unsigned int wsum[8];
    __shared__ int sh_last;
    int n = blockIdx.y;
    int t = threadIdx.x;
    for (int i = t; i < 4096; i += 256) sh[i] = 0;
    __syncthreads();
    int W = 1 << logW, Hin = W >> 1;
    int HW = W << logW;
    for (int pix = blockIdx.x*256 + t; pix < HW; pix += gridDim.x*256) {
        int y = pix >> logW;  int x = pix & (W - 1);
        int y0 = (y - 1) >> 1, x0 = (x - 1) >> 1;
        float wy1 = (y & 1) ? 0.25f : 0.75f;
        float wx1 = (x & 1) ? 0.25f : 0.75f;
        int y1 = y0 + 1, x1 = x0 + 1;
        int xa = (x0 < 0) ? 0 : x0;
        int xb = (x1 > Hin-1) ? Hin-1 : x1;
        float v[NCLS];
        #pragma unroll
        for (int c = 0; c < NCLS; c++) {
            const float* p = in + (size_t)(n*NCLS + c)*Hin*Hin;
            float colA, colB;
            if (y0 < 0)            { colA = p[xa];               colB = p[xb]; }
            else if (y1 > Hin - 1) { colA = p[(Hin-1)*Hin + xa]; colB = p[(Hin-1)*Hin + xb]; }
            else {
                colA = (1.f - wy1)*p[y0*Hin + xa] + wy1*p[y1*Hin + xa];
                colB = (1.f - wy1)*p[y0*Hin + xb] + wy1*p[y1*Hin + xb];
            }
            float vv;
            if (x0 < 0)            vv = colA;
            else if (x1 > Hin - 1) vv = colB;
            else                   vv = (1.f - wx1)*colA + wx1*colB;
            v[c] = vv;
            out[(size_t)(n*NCLS + c)*HW + pix] = vv;
        }
        float hi = fmaxf(v[0], v[1]), lo = fminf(v[0], v[1]);
        float m1 = fmaxf(hi, v[2]);
        float m2 = fmaxf(lo, fminf(hi, v[2]));
        unsigned int key = fkey(m2 - m1);
        g_keys[n*KEYSTRIDE + pix] = key;
        atomicAdd(&sh[key >> 20], 1u);
    }
    __syncthreads();
    for (int i = t; i < 4096; i += 256) {
        unsigned int v = sh[i];
        if (v) atomicAdd(&g_hist2[n*4096 + i], v);
    }
    __threadfence();
    if (t == 0) {
        int old = atomicAdd(&g_done1[n], 1);
        sh_last = (old == (int)gridDim.x - 1);
    }
    __syncthreads();
    if (!sh_last) return;
    unsigned int* gh = g_hist2 + n*4096;
    int lane = t & 31, wrp = t >> 5;
    int base = 4095 - (t << 4);
    unsigned int h[16];
    unsigned int sum = 0;
    #pragma unroll
    for (int j = 0; j < 16; j++) { h[j] = gh[base - j]; sum += h[j]; }
    unsigned int v = sum;
    #pragma unroll
    for (int off = 1; off < 32; off <<= 1) {
        unsigned int u = __shfl_up_sync(0xffffffffu, v, off);
        if (lane >= off) v += u;
    }
    if (lane == 31) wsum[wrp] = v;
    __syncthreads();
    if (wrp == 0 && lane < 8) {
        unsigned int w = wsum[lane];
        #pragma unroll
        for (int off = 1; off < 8; off <<= 1) {
            unsigned int u = __shfl_up_sync(0xffu, w, off);
            if (lane >= off) w += u;
        }
        wsum[lane] = w;
    }
    __syncthreads();
    unsigned int incl = v + (wrp ? wsum[wrp-1] : 0u);
    unsigned int excl = incl - sum;
    if (excl < TOPK && TOPK <= incl) {
        unsigned int c = excl;
        #pragma unroll
        for (int j = 0; j < 16; j++) {
            if (c + h[j] >= TOPK) { g_bstar[n] = base - j; g_kRem[n] = (int)(TOPK - c); break; }
            c += h[j];
        }
    }
    #pragma unroll
    for (int j = 0; j < 16; j++) gh[base - j] = 0;
    if (t == 0) { g_selCount[n] = 0; g_candCount[n] = 0; g_done1[n] = 0; }
}

// ---------------- K2: compact + level-2 hist; last block: scan + exact tie-rank ----------------
__global__ void __launch_bounds__(1024)
compact_sel(int HW) {
    __shared__ unsigned int h2s[1024];
    __shared__ unsigned int wsum[32];
    __shared__ int sh_last, sh_b2, sh_k2, s3cnt;
    __shared__ u32 s3[C3CAP];
    int n = blockIdx.y;
    int t = threadIdx.x;
    int lane = t & 31, wrp = t >> 5;
    int bstar = g_bstar[n];
    const unsigned int* keys = g_keys + n*KEYSTRIDE;
    unsigned long long* cand = g_cand + (size_t)n*KEYSTRIDE;
    h2s[t] = 0;
    __syncthreads();
    for (int i = blockIdx.x*1024 + t; i < HW; i += gridDim.x*1024) {
        unsigned int key = keys[i];
        int b = (int)(key >> 20);
        bool isSel  = (b > bstar);
        bool isCand = (b == bstar);
        u32 mS = __ballot_sync(0xffffffffu, isSel);
        u32 mC = __ballot_sync(0xffffffffu, isCand);
        if (isSel) {
            int ldr = __ffs(mS) - 1;
            int base;
            if (lane == ldr) base = atomicAdd(&g_selCount[n], __popc(mS));
            base = __shfl_sync(mS, base, ldr);
            g_idx[n*PPB + base + __popc(mS & ((1u << lane) - 1u))] = i;
        }
        if (isCand) {
            int ldr = __ffs(mC) - 1;
            int base;
            if (lane == ldr) base = atomicAdd(&g_candCount[n], __popc(mC));
            base = __shfl_sync(mC, base, ldr);
            cand[base + __popc(mC & ((1u << lane) - 1u))] =
                (((unsigned long long)(key & 0xFFFFFu)) << 18) | (unsigned int)((~i) & 0x3FFFF);
            atomicAdd(&h2s[(key >> 10) & 1023u], 1u);
        }
    }
    __syncthreads();
    if (h2s[t]) atomicAdd(&g_h2[n*1024 + t], h2s[t]);
    __threadfence();
    if (t == 0) {
        int old = atomicAdd(&g_done2[n], 1);
        sh_last = (old == (int)gridDim.x - 1);
        s3cnt = 0;
    }
    __syncthreads();
    if (!sh_last) return;
    // ---- level-2 resolve: bin (1023 - t), descending scan ----
    unsigned int val = g_h2[n*1024 + (1023 - t)];
    g_h2[n*1024 + (1023 - t)] = 0;            // clean for next step
    unsigned int v = val;
    #pragma unroll
    for (int off = 1; off < 32; off <<= 1) {
        unsigned int u = __shfl_up_sync(0xffffffffu, v, off);
        if (lane >= off) v += u;
    }
    if (lane == 31) wsum[wrp] = v;
    __syncthreads();
    if (wrp == 0) {
        unsigned int w = wsum[lane];
        #pragma unroll
        for (int off = 1; off < 32; off <<= 1) {
            unsigned int u = __shfl_up_sync(0xffffffffu, w, off);
            if (lane >= off) w += u;
        }
        wsum[lane] = w;
    }
    __syncthreads();
    unsigned int need = (unsigned int)g_kRem[n];
    unsigned int incl = v + (wrp ? wsum[wrp-1] : 0u);
    unsigned int excl = incl - val;
    if (excl < need && need <= incl) { sh_b2 = 1023 - t; sh_k2 = (int)(need - excl); }
    __syncthreads();
    u32 b2star = (u32)sh_b2;
    int k2 = sh_k2;
    int m = g_candCount[n];
    // ---- pass: b2 > b2star -> emit; b2 == b2star -> s3 ----
    for (int i = t; i < m; i += 1024) {
        u64 c = cand[i];
        u32 b2 = (u32)(c >> 28) & 1023u;
        if (b2 > b2star) {
            int p = atomicAdd(&g_selCount[n], 1);
            g_idx[n*PPB + p] = (int)((~c) & 0x3FFFF);
        } else if (b2 == b2star) {
            int p = atomicAdd(&s3cnt, 1);
            if (p < C3CAP) s3[p] = (u32)(c & 0xFFFFFFFu);
        }
    }
    __syncthreads();
    int c3 = s3cnt;
    if (c3 <= C3CAP) {
        for (int j = t; j < c3; j += 1024) {
            u32 vv = s3[j];
            int r = 0;
            for (int q = 0; q < c3; q++) r += (s3[q] > vv);
            if (r < k2) {
                int p = atomicAdd(&g_selCount[n], 1);
                g_idx[n*PPB + p] = (int)((~vv) & 0x3FFFF);
            }
        }
    } else {
        // correct-but-slow fallback (distribution makes this unreachable)
        for (int i = t; i < m; i += 1024) {
            u64 c = cand[i];
            if (((u32)(c >> 28) & 1023u) != b2star) continue;
            u32 vv = (u32)(c & 0xFFFFFFFu);
            int r = 0;
            for (int q = 0; q < m; q++) {
                u64 cc = cand[q];
                if (((u32)(cc >> 28) & 1023u) == b2star && (u32)(cc & 0xFFFFFFFu) > vv) r++;
            }
            if (r < k2) {
                int p = atomicAdd(&g_selCount[n], 1);
                g_idx[n*PPB + p] = (int)((~vv) & 0x3FFFF);
            }
        }
    }
    if (t == 0) g_done2[n] = 0;
}

// ---------------- unified MLP: fragment-major, 2x8 warp tiling, NP-plane split ----------------
template<int NP>
__global__ void __launch_bounds__(256, 1)
mma_mlp(const float* __restrict__ coarse,
        const float* __restrict__ b1, const float* __restrict__ b2, const float* __restrict__ b3,
        const float* __restrict__ wph, const float* __restrict__ bph,
        float* __restrict__ sem, int HW, int logW) {
    extern __shared__ float dynsm[];
    char* smc = (char*)dynsm;
    u32* XP = (u32*)smc;
    u32* WP = (u32*)(smc + NP*PLB);
    const int MISC = 2*NP*PLB;
    float* bias_s  = (float*)(smc + MISC);
    float* wps     = (float*)(smc + MISC + 512);
    float* hsum    = (float*)(smc + MISC + 2096);
    float* scoarse = (float*)(smc + MISC + 3632);

    __shared__ int   sx0[128], sy0[128];
    __shared__ float sw0[128], sw1[128], sw2[128], sw3[128];

    int tid = threadIdx.x, lane = tid & 31, wrp = tid >> 5;
    int pBase = blockIdx.x * 128;
    int n = pBase >> 13;

    {
        float4 z = make_float4(0.f, 0.f, 0.f, 0.f);
        float4* xz = (float4*)smc;
        #pragma unroll
        for (int q = 0; q < NP*9; q++) xz[tid + 256*q] = z;
    }
    if (tid < 128) {
        int id = g_idx[pBase + tid];
        int W = 1 << logW;
        float inv = 1.f / (float)W;
        float px = ((float)(id & (W-1)) + 0.5f) * inv;
        float py = ((float)(id >> logW) + 0.5f) * inv;
        float fx = px * 256.f - 0.5f, fy = py * 256.f - 0.5f;
        float fx0 = floorf(fx), fy0 = floorf(fy);
        float wx1 = fx - fx0, wy1 = fy - fy0;
        sx0[tid] = (int)fx0; sy0[tid] = (int)fy0;
        sw0[tid] = (1.f-wx1)*(1.f-wy1);
        sw1[tid] = wx1*(1.f-wy1);
        sw2[tid] = (1.f-wx1)*wy1;
        sw3[tid] = wx1*wy1;
        float cx = px*128.f - 0.5f, cy = py*128.f - 0.5f;
        float cx0f = floorf(cx), cy0f = floorf(cy);
        int x0 = (int)cx0f, y0 = (int)cy0f;
        float cwx = cx - cx0f, cwy = cy - cy0f;
        #pragma unroll
        for (int cc = 0; cc < NCLS; cc++) {
            const float* p = coarse + (size_t)(n*NCLS + cc)*CH*CH;
            float acc = 0.f;
            if (x0 >= 0   && y0 >= 0  ) acc += (1.f-cwx)*(1.f-cwy)*p[y0*CH + x0];
            if (x0+1 < CH && y0 >= 0  ) acc += cwx*(1.f-cwy)*p[y0*CH + x0+1];
            if (x0 >= 0   && y0+1 < CH) acc += (1.f-cwx)*cwy*p[(y0+1)*CH + x0];
            if (x0+1 < CH && y0+1 < CH) acc += cwx*cwy*p[(y0+1)*CH + x0+1];
            scoarse[cc*128 + tid] = acc;
        }
    }
    for (int j = tid; j < 3*KIN; j += 256) wps[j] = wph[j];
    __syncthreads();

    const float* fbase = g_featT + (size_t)n*FH*FH*NIN;
    int ch0 = lane << 2;
    #pragma unroll 4
    for (int it = 0; it < 16; it++) {
        int pt = wrp + it*8;
        int x0 = sx0[pt], y0 = sy0[pt];
        bool xv0 = (x0 >= 0), xv1 = (x0+1 < FH), yv0 = (y0 >= 0), yv1 = (y0+1 < FH);
        float a0 = 0.f, a1 = 0.f, a2 = 0.f, a3 = 0.f;
        if (xv0 && yv0) { float w = sw0[pt]; float4 v = *(const float4*)(fbase + (size_t)((y0  )*FH + x0  )*NIN + ch0);
                          a0 += w*v.x; a1 += w*v.y; a2 += w*v.z; a3 += w*v.w; }
        if (xv1 && yv0) { float w = sw1[pt]; float4 v = *(const float4*)(fbase + (size_t)((y0  )*FH + x0+1)*NIN + ch0);
                          a0 += w*v.x; a1 += w*v.y; a2 += w*v.z; a3 += w*v.w; }
        if (xv0 && yv1) { float w = sw2[pt]; float4 v = *(const float4*)(fbase + (size_t)((y0+1)*FH + x0  )*NIN + ch0);
                          a0 += w*v.x; a1 += w*v.y; a2 += w*v.z; a3 += w*v.w; }
        if (xv1 && yv1) { float w = sw3[pt]; float4 v = *(const float4*)(fbase + (size_t)((y0+1)*FH + x0+1)*NIN + ch0);
                          a0 += w*v.x; a1 += w*v.y; a2 += w*v.z; a3 += w*v.w; }
        int ad0 = xf_addr(pt, (lane << 1));
        int ad1 = xf_addr(pt, (lane << 1) + 1);
        float r0 = a0, r1 = a1, r2 = a2, r3 = a3;
        #pragma unroll
        for (int p = 0; p < NP; p++) {
            u32 pkA = pack_bf16x2(r0, r1);
            u32 pkB = pack_bf16x2(r2, r3);
            XP[p*PLU + ad0] = pkA;
            XP[p*PLU + ad1] = pkB;
            r0 -= bf16lo_f(pkA); r1 -= bf16hi_f(pkA);
            r2 -= bf16lo_f(pkB); r3 -= bf16hi_f(pkB);
        }
    }
    if (tid < 128) {
        float c0 = scoarse[tid], c1 = scoarse[128 + tid], c2 = scoarse[256 + tid];
        int ad64 = xf_addr(tid, 64);
        int ad65 = xf_addr(tid, 65);
        float r0 = c0, r1 = c1, r2 = c2, r3 = 0.f;
        #pragma unroll
        for (int p = 0; p < NP; p++) {
            u32 pkA = pack_bf16x2(r0, r1);
            u32 pkB = pack_bf16x2(r2, r3);
            XP[p*PLU + ad64] = pkA;
            XP[p*PLU + ad65] = pkB;
            r0 -= bf16lo_f(pkA); r1 -= bf16hi_f(pkA);
            r2 -= bf16lo_f(pkB); r3 -= bf16hi_f(pkB);
        }
        #pragma unroll
        for (int c = 0; c < NCLS; c++)
            hsum[c*128 + tid] = wps[c*KIN + 128]*c0 + wps[c*KIN + 129]*c1 + wps[c*KIN + 130]*c2 + __ldg(&bph[c]);
    }
    __syncthreads();

    const int NPROD = (NP == 2) ? 3 : 6;
    const int PA[6] = {0, 0, 1, 1, 0, 2};
    const int PB[6] = {0, 1, 0, 1, 2, 0};

    int g = lane >> 2;
    int tig = lane & 3;
    int wm = wrp & 3;        // 2 m-tiles: 2wm, 2wm+1
    int wn = wrp >> 2;       // nt range wn*8 .. wn*8+7

    for (int l = 0; l < 3; l++) {
        {
            const float4* wsrc = (const float4*)(g_Wf + (size_t)l*3*PLU);
            float4* wdst = (float4*)WP;
            #pragma unroll
            for (int q = 0; q < NP*9; q++) wdst[tid + 256*q] = wsrc[tid + 256*q];
        }
        const float* Bp = (l == 0) ? b1 : ((l == 1) ? b2 : b3);
        if (tid < 128) bias_s[tid] = __ldg(&Bp[tid]);
        __syncthreads();

        float acc[2][8][4];
        #pragma unroll
        for (int mi = 0; mi < 2; mi++)
            #pragma unroll
            for (int j = 0; j < 8; j++) {
                acc[mi][j][0] = 0.f; acc[mi][j][1] = 0.f;
                acc[mi][j][2] = 0.f; acc[mi][j][3] = 0.f;
            }
        for (int ks = 0; ks < 9; ks++) {
            uint4 afA[NP], afB[NP];
            #pragma unroll
            for (int p = 0; p < NP; p++) {
                afA[p] = *(const uint4*)(XP + p*PLU + ((((2*wm  )*9 + ks)*32 + lane) << 2));
                afB[p] = *(const uint4*)(XP + p*PLU + ((((2*wm+1)*9 + ks)*32 + lane) << 2));
            }
            #pragma unroll
            for (int j = 0; j < 8; j++) {
                int nt = wn*8 + j;
                int boff = (((ks*16 + nt)*32 + lane) << 1);
                uint2 bfr[NP];
                #pragma unroll
                for (int p = 0; p < NP; p++)
                    bfr[p] = *(const uint2*)(WP + p*PLU + boff);
                #pragma unroll
                for (int q = 0; q < NPROD; q++) {
                    mma16816(acc[0][j], afA[PA[q]].x, afA[PA[q]].y, afA[PA[q]].z, afA[PA[q]].w,
                             bfr[PB[q]].x, bfr[PB[q]].y);
                    mma16816(acc[1][j], afB[PA[q]].x, afB[PA[q]].y, afB[PA[q]].z, afB[PA[q]].w,
                             bfr[PB[q]].x, bfr[PB[q]].y);
                }
            }
        }
        __syncthreads();

        #pragma unroll
        for (int mi = 0; mi < 2; mi++) {
            int mt = 2*wm + mi;
            #pragma unroll
            for (int j = 0; j < 8; j++) {
                int nt = wn*8 + j;
                int col = nt*8 + (tig << 1);
                float bA = bias_s[col], bB = bias_s[col + 1];
                float v0 = fmaxf(acc[mi][j][0] + bA, 0.f);
                float v1 = fmaxf(acc[mi][j][1] + bB, 0.f);
                float v2 = fmaxf(acc[mi][j][2] + bA, 0.f);
                float v3 = fmaxf(acc[mi][j][3] + bB, 0.f);
                int pi = nt*4 + tig;
                int adA = xf_addr(mt*16 + g, pi);
                float r0 = v0, r1 = v1, r2 = v2, r3 = v3;
                #pragma unroll
                for (int p = 0; p < NP; p++) {
                    u32 pkA = pack_bf16x2(r0, r1);
                    u32 pkB = pack_bf16x2(r2, r3);
                    *(uint2*)(XP + p*PLU + adA) = make_uint2(pkA, pkB);
                    r0 -= bf16lo_f(pkA); r1 -= bf16hi_f(pkA);
                    r2 -= bf16lo_f(pkB); r3 -= bf16hi_f(pkB);
                }
            }
        }
        __syncthreads();
    }

    if (tid < 128) {
        float s0 = 0.f, s1 = 0.f, s2 = 0.f;
        #pragma unroll 8
        for (int kp = 0; kp < 64; kp++) {
            int ad = xf_addr(tid, kp);
            float x0 = 0.f, x1 = 0.f;
            #pragma unroll
            for (int p = 0; p < NP; p++) {
                u32 v = XP[p*PLU + ad];
                x0 += bf16lo_f(v); x1 += bf16hi_f(v);
            }
            int k = kp << 1;
            s0 += wps[k]*x0 + wps[k+1]*x1;
            s1 += wps[KIN + k]*x0 + wps[KIN + k + 1]*x1;
            s2 += wps[2*KIN + k]*x0 + wps[2*KIN + k + 1]*x1;
        }
        int id = g_idx[pBase + tid];
        sem[(size_t)(n*NCLS + 0)*HW + id] = hsum[tid] + s0;
        sem[(size_t)(n*NCLS + 1)*HW + id] = hsum[128 + tid] + s1;
        sem[(size_t)(n*NCLS + 2)*HW + id] = hsum[256 + tid] + s2;
    }
}

// ---------------- launch ----------------
extern "C" void kernel_launch(void* const* d_in, const int* in_sizes, int n_in,
                              void* d_out, int out_size) {
    const float* coarse = (const float*)d_in[0];
    const float* feat   = (const float*)d_in[1];
    const float* w1 = (const float*)d_in[2];
    const float* b1 = (const float*)d_in[3];
    const float* w2 = (const float*)d_in[4];
    const float* b2 = (const float*)d_in[5];
    const float* w3 = (const float*)d_in[6];
    const float* b3 = (const float*)d_in[7];
    const float* wp = (const float*)d_in[8];
    const float* bp = (const float*)d_in[9];
    float* out = (float*)d_out;

    float* sem256;
    cudaGetSymbolAddress((void**)&sem256, g_sem256);

    static cudaStream_t sSide = nullptr;
    static cudaEvent_t evFork = nullptr, evJoin = nullptr;
    if (sSide == nullptr) {
        cudaStreamCreateWithFlags(&sSide, cudaStreamNonBlocking);
        cudaEventCreateWithFlags(&evFork, cudaEventDisableTiming);
        cudaEventCreateWithFlags(&evJoin, cudaEventDisableTiming);
    }

    const int SM3 = 2*3*PLB + 5200;   // 226,384 B
    const int SM2 = 2*2*PLB + 5200;   // 152,656 B
    cudaFuncSetAttribute(mma_mlp<3>, cudaFuncAttributeMaxDynamicSharedMemorySize, SM3);
    cudaFuncSetAttribute(mma_mlp<2>, cudaFuncAttributeMaxDynamicSharedMemorySize, SM2);

    cudaEventRecord(evFork, 0);
    cudaStreamWaitEvent(sSide, evFork, 0);
    transpose_kernel<<<dim3(2048, 4, 4), dim3(32, 8), 0, sSide>>>(feat);
    cudaEventRecord(evJoin, sSide);

    prep_kernel<<<256, 256>>>(w1, w2, w3);

    for (int step = 0; step < 2; step++) {
        int logW = (step == 0) ? 8 : 9;
        int HW   = 1 << (2*logW);
        const float* semIn = (step == 0) ? coarse : sem256;
        float* semOut      = (step == 0) ? sem256 : out;

        upsample_sel<<<dim3(HW/1024, NB), 256>>>(semIn, semOut, logW);
        compact_sel<<<dim3(HW/4096, NB), 1024>>>(HW);

        if (step == 0) {
            cudaStreamWaitEvent(0, evJoin, 0);
            mma_mlp<3><<<PTOT/128, 256, SM3>>>(coarse, b1, b2, b3, wp, bp, semOut, HW, logW);
        } else {
            mma_mlp<2><<<PTOT/128, 256, SM2>>>(coarse, b1, b2, b3, wp, bp, semOut, HW, logW);
        }
    }
}

// round 14
// speedup vs baseline: 1.3593x; 1.1363x over previous
#include <cuda_runtime.h>
#include <math.h>

typedef unsigned int       u32;
typedef unsigned long long u64;
typedef unsigned short     u16;

#define NB   4
#define NCLS 3
#define FH   256
#define CH   128
#define NIN  128
#define KIN  131
#define PPB  8192
#define PTOT 32768
#define KEYSTRIDE 262144
#define TOPK 8192u

#define PLU    9216               // u32 per plane
#define PLB    36864              // bytes per plane
#define C3CAP  2048

// ---------------- scratch ----------------
__device__ float        g_featT[(size_t)NB*FH*FH*NIN];
__device__ float        g_sem256[NB*NCLS*256*256];
__device__ unsigned int g_keys[NB*KEYSTRIDE];
__device__ unsigned int g_hist2[NB*4096];
__device__ unsigned int g_h2[NB*1024];
__device__ unsigned long long g_cand[(size_t)NB*KEYSTRIDE];
__device__ int          g_bstar[NB];
__device__ int          g_kRem[NB];
__device__ int          g_selCount[NB];
__device__ int          g_candCount[NB];
__device__ int          g_done1[NB];
__device__ int          g_done2[NB];
__device__ int          g_idx[PTOT];
__device__ __align__(16) u32 g_Wf[3*3*PLU];   // [layer][plane][fragment-major]

__device__ __forceinline__ unsigned int fkey(float f) {
    unsigned int u = __float_as_uint(f);
    return (u & 0x80000000u) ? ~u : (u | 0x80000000u);
}
__device__ __forceinline__ u32 pack_bf16x2(float lo_val, float hi_val) {
    u32 r;
    asm("cvt.rn.bf16x2.f32 %0, %1, %2;" : "=r"(r) : "f"(hi_val), "f"(lo_val));
    return r;
}
__device__ __forceinline__ float bf16lo_f(u32 p) { return __uint_as_float(p << 16); }
__device__ __forceinline__ float bf16hi_f(u32 p) { return __uint_as_float(p & 0xFFFF0000u); }

__device__ __forceinline__ void mma16816(float* d, u32 a0, u32 a1, u32 a2, u32 a3, u32 b0, u32 b1) {
    asm volatile("mma.sync.aligned.m16n8k16.row.col.f32.bf16.bf16.f32 {%0,%1,%2,%3}, {%4,%5,%6,%7}, {%8,%9}, {%0,%1,%2,%3};" : "+f"(d[0]), "+f"(d[1]), "+f"(d[2]), "+f"(d[3]) : "r"(a0), "r"(a1), "r"(a2), "r"(a3), "r"(b0), "r"(b1));
}

// X fragment-major address (u32 units) for block-point pt (0..127), k-pair pi (0..71)
__device__ __forceinline__ int xf_addr(int pt, int pi) {
    int w = pt >> 4, r = pt & 15;
    int g = r & 7, rh = r >> 3;
    int ks = pi >> 3, sub = pi & 7;
    int tg = sub & 3, kh = sub >> 2;
    return (((w*9 + ks)*32 + (g << 2) + tg) << 2) + rh + (kh << 1);
}

// ---------------- one-time prep: hist zero + fragment-major 3-plane W pack ----------------
__global__ void prep_kernel(const float* __restrict__ w1, const float* __restrict__ w2,
                            const float* __restrict__ w3) {
    int i = blockIdx.x*blockDim.x + threadIdx.x;
    int stride = gridDim.x*blockDim.x;
    for (int j = i; j < NB*4096; j += stride) g_hist2[j] = 0;
    for (int j = i; j < NB*1024; j += stride) g_h2[j] = 0;
    if (i < NB) { g_done1[i] = 0; g_done2[i] = 0; g_selCount[i] = 0; g_candCount[i] = 0; }
    for (int j = i; j < 3*PLU; j += stride) {
        int l = j / PLU; int e = j - l*PLU;
        int reg = e & 1;
        int lane = (e >> 1) & 31;
        int nt = (e >> 6) & 15;
        int ks = e >> 10;
        int n  = nt*8 + (lane >> 2);
        int k0 = ks*16 + (lane & 3)*2 + (reg << 3);
        const float* w = (l == 0) ? w1 : ((l == 1) ? w2 : w3);
        float v0 = (k0     < KIN) ? w[n*KIN + k0]     : 0.f;
        float v1 = (k0 + 1 < KIN) ? w[n*KIN + k0 + 1] : 0.f;
        #pragma unroll
        for (int p = 0; p < 3; p++) {
            u32 pk = pack_bf16x2(v0, v1);
            g_Wf[(l*3 + p)*PLU + e] = pk;
            v0 -= bf16lo_f(pk); v1 -= bf16hi_f(pk);
        }
    }
}

// ---------------- features NCHW -> NHWC ----------------
__global__ void transpose_kernel(const float* __restrict__ f) {
    __shared__ float tile[32][33];
    int n = blockIdx.z;
    int pix0 = blockIdx.x * 32;
    int c0   = blockIdx.y * 32;
    int tx = threadIdx.x, ty = threadIdx.y;
    #pragma unroll
    for (int i = ty; i < 32; i += 8)
        tile[i][tx] = f[(size_t)(n*NIN + c0 + i)*(FH*FH) + pix0 + tx];
    __syncthreads();
    #pragma unroll
    for (int i = ty; i < 32; i += 8)
        g_featT[(size_t)(n*(FH*FH) + pix0 + i)*NIN + c0 + tx] = tile[tx][i];
}

// ---------------- K1: upsample + keys + hist; last block resolves ----------------
__global__ void upsample_sel(const float* __restrict__ in, float* __restrict__ out, int logW) {
    __shared__ unsigned int sh[4096];
    __shared__ unsigned int wsum[8];
    __shared__ int sh_last;
    int n = blockIdx.y;
    int t = threadIdx.x;
    for (int i = t; i < 4096; i += 256) sh[i] = 0;
    __syncthreads();
    int W = 1 << logW, Hin = W >> 1;
    int HW = W << logW;
    for (int pix = blockIdx.x*256 + t; pix < HW; pix += gridDim.x*256) {
        int y = pix >> logW;  int x = pix & (W - 1);
        int y0 = (y - 1) >> 1, x0 = (x - 1) >> 1;
        float wy1 = (y & 1) ? 0.25f : 0.75f;
        float wx1 = (x & 1) ? 0.25f : 0.75f;
        int y1 = y0 + 1, x1 = x0 + 1;
        int xa = (x0 < 0) ? 0 : x0;
        int xb = (x1 > Hin-1) ? Hin-1 : x1;
        float v[NCLS];
        #pragma unroll
        for (int c = 0; c < NCLS; c++) {
            const float* p = in + (size_t)(n*NCLS + c)*Hin*Hin;
            float colA, colB;
            if (y0 < 0)            { colA = p[xa];               colB = p[xb]; }
            else if (y1 > Hin - 1) { colA = p[(Hin-1)*Hin + xa]; colB = p[(Hin-1)*Hin + xb]; }
            else {
                colA = (1.f - wy1)*p[y0*Hin + xa] + wy1*p[y1*Hin + xa];
                colB = (1.f - wy1)*p[y0*Hin + xb] + wy1*p[y1*Hin + xb];
            }
            float vv;
            if (x0 < 0)            vv = colA;
            else if (x1 > Hin - 1) vv = colB;
            else                   vv = (1.f - wx1)*colA + wx1*colB;
            v[c] = vv;
            out[(size_t)(n*NCLS + c)*HW + pix] = vv;
        }
        float hi = fmaxf(v[0], v[1]), lo = fminf(v[0], v[1]);
        float m1 = fmaxf(hi, v[2]);
        float m2 = fmaxf(lo, fminf(hi, v[2]));
        unsigned int key = fkey(m2 - m1);
        g_keys[n*KEYSTRIDE + pix] = key;
        atomicAdd(&sh[key >> 20], 1u);
    }
    __syncthreads();
    for (int i = t; i < 4096; i += 256) {
        unsigned int v = sh[i];
        if (v) atomicAdd(&g_hist2[n*4096 + i], v);
    }
    __threadfence();
    if (t == 0) {
        int old = atomicAdd(&g_done1[n], 1);
        sh_last = (old == (int)gridDim.x - 1);
    }
    __syncthreads();
    if (!sh_last) return;
    unsigned int* gh = g_hist2 + n*4096;
    int lane = t & 31, wrp = t >> 5;
    int base = 4095 - (t << 4);
    unsigned int h[16];
    unsigned int sum = 0;
    #pragma unroll
    for (int j = 0; j < 16; j++) { h[j] = gh[base - j]; sum += h[j]; }
    unsigned int v = sum;
    #pragma unroll
    for (int off = 1; off < 32; off <<= 1) {
        unsigned int u = __shfl_up_sync(0xffffffffu, v, off);
        if (lane >= off) v += u;
    }
    if (lane == 31) wsum[wrp] = v;
    __syncthreads();
    if (wrp == 0 && lane < 8) {
        unsigned int w = wsum[lane];
        #pragma unroll
        for (int off = 1; off < 8; off <<= 1) {
            unsigned int u = __shfl_up_sync(0xffu, w, off);
            if (lane >= off) w += u;
        }
        wsum[lane] = w;
    }
    __syncthreads();
    unsigned int incl = v + (wrp ? wsum[wrp-1] : 0u);
    unsigned int excl = incl - sum;
    if (excl < TOPK && TOPK <= incl) {
        unsigned int c = excl;
        #pragma unroll
        for (int j = 0; j < 16; j++) {
            if (c + h[j] >= TOPK) { g_bstar[n] = base - j; g_kRem[n] = (int)(TOPK - c); break; }
            c += h[j];
        }
    }
    #pragma unroll
    for (int j = 0; j < 16; j++) gh[base - j] = 0;
    if (t == 0) { g_selCount[n] = 0; g_candCount[n] = 0; g_done1[n] = 0; }
}

// ---------------- K2: compact + level-2 hist; last block: scan + exact tie-rank ----------------
__global__ void __launch_bounds__(1024)
compact_sel(int HW) {
    __shared__ unsigned int h2s[1024];
    __shared__ unsigned int wsum[32];
    __shared__ int sh_last, sh_b2, sh_k2, s3cnt;
    __shared__ u32 s3[C3CAP];
    int n = blockIdx.y;
    int t = threadIdx.x;
    int lane = t & 31, wrp = t >> 5;
    int bstar = g_bstar[n];
    const unsigned int* keys = g_keys + n*KEYSTRIDE;
    unsigned long long* cand = g_cand + (size_t)n*KEYSTRIDE;
    h2s[t] = 0;
    __syncthreads();
    for (int i = blockIdx.x*1024 + t; i < HW; i += gridDim.x*1024) {
        unsigned int key = keys[i];
        int b = (int)(key >> 20);
        bool isSel  = (b > bstar);
        bool isCand = (b == bstar);
        u32 mS = __ballot_sync(0xffffffffu, isSel);
        u32 mC = __ballot_sync(0xffffffffu, isCand);
        if (isSel) {
            int ldr = __ffs(mS) - 1;
            int base;
            if (lane == ldr) base = atomicAdd(&g_selCount[n], __popc(mS));
            base = __shfl_sync(mS, base, ldr);
            g_idx[n*PPB + base + __popc(mS & ((1u << lane) - 1u))] = i;
        }
        if (isCand) {
            int ldr = __ffs(mC) - 1;
            int base;
            if (lane == ldr) base = atomicAdd(&g_candCount[n], __popc(mC));
            base = __shfl_sync(mC, base, ldr);
            cand[base + __popc(mC & ((1u << lane) - 1u))] =
                (((unsigned long long)(key & 0xFFFFFu)) << 18) | (unsigned int)((~i) & 0x3FFFF);
            atomicAdd(&h2s[(key >> 10) & 1023u], 1u);
        }
    }
    __syncthreads();
    if (h2s[t]) atomicAdd(&g_h2[n*1024 + t], h2s[t]);
    __threadfence();
    if (t == 0) {
        int old = atomicAdd(&g_done2[n], 1);
        sh_last = (old == (int)gridDim.x - 1);
        s3cnt = 0;
    }
    __syncthreads();
    if (!sh_last) return;
    unsigned int val = g_h2[n*1024 + (1023 - t)];
    g_h2[n*1024 + (1023 - t)] = 0;
    unsigned int v = val;
    #pragma unroll
    for (int off = 1; off < 32; off <<= 1) {
        unsigned int u = __shfl_up_sync(0xffffffffu, v, off);
        if (lane >= off) v += u;
    }
    if (lane == 31) wsum[wrp] = v;
    __syncthreads();
    if (wrp == 0) {
        unsigned int w = wsum[lane];
        #pragma unroll
        for (int off = 1; off < 32; off <<= 1) {
            unsigned int u = __shfl_up_sync(0xffffffffu, w, off);
            if (lane >= off) w += u;
        }
        wsum[lane] = w;
    }
    __syncthreads();
    unsigned int need = (unsigned int)g_kRem[n];
    unsigned int incl = v + (wrp ? wsum[wrp-1] : 0u);
    unsigned int excl = incl - val;
    if (excl < need && need <= incl) { sh_b2 = 1023 - t; sh_k2 = (int)(need - excl); }
    __syncthreads();
    u32 b2star = (u32)sh_b2;
    int k2 = sh_k2;
    int m = g_candCount[n];
    for (int i = t; i < m; i += 1024) {
        u64 c = cand[i];
        u32 b2 = (u32)(c >> 28) & 1023u;
        if (b2 > b2star) {
            int p = atomicAdd(&g_selCount[n], 1);
            g_idx[n*PPB + p] = (int)((~c) & 0x3FFFF);
        } else if (b2 == b2star) {
            int p = atomicAdd(&s3cnt, 1);
            if (p < C3CAP) s3[p] = (u32)(c & 0xFFFFFFFu);
        }
    }
    __syncthreads();
    int c3 = s3cnt;
    if (c3 <= C3CAP) {
        for (int j = t; j < c3; j += 1024) {
            u32 vv = s3[j];
            int r = 0;
            for (int q = 0; q < c3; q++) r += (s3[q] > vv);
            if (r < k2) {
                int p = atomicAdd(&g_selCount[n], 1);
                g_idx[n*PPB + p] = (int)((~vv) & 0x3FFFF);
            }
        }
    } else {
        for (int i = t; i < m; i += 1024) {
            u64 c = cand[i];
            if (((u32)(c >> 28) & 1023u) != b2star) continue;
            u32 vv = (u32)(c & 0xFFFFFFFu);
            int r = 0;
            for (int q = 0; q < m; q++) {
                u64 cc = cand[q];
                if (((u32)(cc >> 28) & 1023u) == b2star && (u32)(cc & 0xFFFFFFFu) > vv) r++;
            }
            if (r < k2) {
                int p = atomicAdd(&g_selCount[n], 1);
                g_idx[n*PPB + p] = (int)((~vv) & 0x3FFFF);
            }
        }
    }
    if (t == 0) g_done2[n] = 0;
}

// ---------------- unified MLP: X in smem, W from global (L2-hot), 2x8 warp tiling ----------------
template<int NP>
__global__ void __launch_bounds__(256, 2)
mma_mlp(const float* __restrict__ coarse,
        const float* __restrict__ b1, const float* __restrict__ b2, const float* __restrict__ b3,
        const float* __restrict__ wph, const float* __restrict__ bph,
        float* __restrict__ sem, int HW, int logW) {
    extern __shared__ float dynsm[];
    char* smc = (char*)dynsm;
    u32* XP = (u32*)smc;                       // NP planes, fragment-major
    const int MISC = NP*PLB;
    float* bias_s = (float*)(smc + MISC);      // 128 floats
    float* hsum   = (float*)(smc + MISC + 512);// 3*128 floats

    __shared__ int   sx0[128], sy0[128];
    __shared__ float sw0[128], sw1[128], sw2[128], sw3[128];

    int tid = threadIdx.x, lane = tid & 31, wrp = tid >> 5;
    int pBase = blockIdx.x * 128;
    int n = pBase >> 13;

    // zero X planes
    {
        float4 z = make_float4(0.f, 0.f, 0.f, 0.f);
        float4* xz = (float4*)smc;
        #pragma unroll
        for (int q = 0; q < NP*9; q++) xz[tid + 256*q] = z;
    }
    __syncthreads();
    if (tid < 128) {
        int id = g_idx[pBase + tid];
        int W = 1 << logW;
        float inv = 1.f / (float)W;
        float px = ((float)(id & (W-1)) + 0.5f) * inv;
        float py = ((float)(id >> logW) + 0.5f) * inv;
        float fx = px * 256.f - 0.5f, fy = py * 256.f - 0.5f;
        float fx0 = floorf(fx), fy0 = floorf(fy);
        float wx1 = fx - fx0, wy1 = fy - fy0;
        sx0[tid] = (int)fx0; sy0[tid] = (int)fy0;
        sw0[tid] = (1.f-wx1)*(1.f-wy1);
        sw1[tid] = wx1*(1.f-wy1);
        sw2[tid] = (1.f-wx1)*wy1;
        sw3[tid] = wx1*wy1;
        // coarse sample + pack pairs 64/65 + head coarse terms
        float cx = px*128.f - 0.5f, cy = py*128.f - 0.5f;
        float cx0f = floorf(cx), cy0f = floorf(cy);
        int x0 = (int)cx0f, y0 = (int)cy0f;
        float cwx = cx - cx0f, cwy = cy - cy0f;
        float cs[NCLS];
        #pragma unroll
        for (int cc = 0; cc < NCLS; cc++) {
            const float* p = coarse + (size_t)(n*NCLS + cc)*CH*CH;
            float acc = 0.f;
            if (x0 >= 0   && y0 >= 0  ) acc += (1.f-cwx)*(1.f-cwy)*p[y0*CH + x0];
            if (x0+1 < CH && y0 >= 0  ) acc += cwx*(1.f-cwy)*p[y0*CH + x0+1];
            if (x0 >= 0   && y0+1 < CH) acc += (1.f-cwx)*cwy*p[(y0+1)*CH + x0];
            if (x0+1 < CH && y0+1 < CH) acc += cwx*cwy*p[(y0+1)*CH + x0+1];
            cs[cc] = acc;
        }
        int ad64 = xf_addr(tid, 64);
        int ad65 = xf_addr(tid, 65);
        float r0 = cs[0], r1 = cs[1], r2 = cs[2], r3 = 0.f;
        #pragma unroll
        for (int p = 0; p < NP; p++) {
            u32 pkA = pack_bf16x2(r0, r1);
            u32 pkB = pack_bf16x2(r2, r3);
            XP[p*PLU + ad64] = pkA;
            XP[p*PLU + ad65] = pkB;
            r0 -= bf16lo_f(pkA); r1 -= bf16hi_f(pkA);
            r2 -= bf16lo_f(pkB); r3 -= bf16hi_f(pkB);
        }
        #pragma unroll
        for (int c = 0; c < NCLS; c++)
            hsum[c*128 + tid] = __ldg(&wph[c*KIN + 128])*cs[0] + __ldg(&wph[c*KIN + 129])*cs[1]
                              + __ldg(&wph[c*KIN + 130])*cs[2] + __ldg(&bph[c]);
    }
    __syncthreads();

    // feature gather -> X fragment-major planes (warp-per-point)
    const float* fbase = g_featT + (size_t)n*FH*FH*NIN;
    int ch0 = lane << 2;
    #pragma unroll 4
    for (int it = 0; it < 16; it++) {
        int pt = wrp + it*8;
        int x0 = sx0[pt], y0 = sy0[pt];
        bool xv0 = (x0 >= 0), xv1 = (x0+1 < FH), yv0 = (y0 >= 0), yv1 = (y0+1 < FH);
        float a0 = 0.f, a1 = 0.f, a2 = 0.f, a3 = 0.f;
        if (xv0 && yv0) { float w = sw0[pt]; float4 v = *(const float4*)(fbase + (size_t)((y0  )*FH + x0  )*NIN + ch0);
                          a0 += w*v.x; a1 += w*v.y; a2 += w*v.z; a3 += w*v.w; }
        if (xv1 && yv0) { float w = sw1[pt]; float4 v = *(const float4*)(fbase + (size_t)((y0  )*FH + x0+1)*NIN + ch0);
                          a0 += w*v.x; a1 += w*v.y; a2 += w*v.z; a3 += w*v.w; }
        if (xv0 && yv1) { float w = sw2[pt]; float4 v = *(const float4*)(fbase + (size_t)((y0+1)*FH + x0  )*NIN + ch0);
                          a0 += w*v.x; a1 += w*v.y; a2 += w*v.z; a3 += w*v.w; }
        if (xv1 && yv1) { float w = sw3[pt]; float4 v = *(const float4*)(fbase + (size_t)((y0+1)*FH + x0+1)*NIN + ch0);
                          a0 += w*v.x; a1 += w*v.y; a2 += w*v.z; a3 += w*v.w; }
        int ad0 = xf_addr(pt, (lane << 1));
        int ad1 = xf_addr(pt, (lane << 1) + 1);
        float r0 = a0, r1 = a1, r2 = a2, r3 = a3;
        #pragma unroll
        for (int p = 0; p < NP; p++) {
            u32 pkA = pack_bf16x2(r0, r1);
            u32 pkB = pack_bf16x2(r2, r3);
            XP[p*PLU + ad0] = pkA;
            XP[p*PLU + ad1] = pkB;
            r0 -= bf16lo_f(pkA); r1 -= bf16hi_f(pkA);
            r2 -= bf16lo_f(pkB); r3 -= bf16hi_f(pkB);
        }
    }
    __syncthreads();

    const int NPROD = (NP == 2) ? 3 : 6;
    const int PA[6] = {0, 0, 1, 1, 0, 2};
    const int PB[6] = {0, 1, 0, 1, 2, 0};

    int g = lane >> 4 ? 0 : 0;   // placeholder to keep var names aligned
    g = lane >> 2;
    int tig = lane & 3;
    int wm = wrp & 3;
    int wn = wrp >> 2;

    for (int l = 0; l < 3; l++) {
        const float* Bp = (l == 0) ? b1 : ((l == 1) ? b2 : b3);
        if (tid < 128) bias_s[tid] = __ldg(&Bp[tid]);
        __syncthreads();
        const u32* Wg = g_Wf + (size_t)l*3*PLU;

        float acc[2][8][4];
        #pragma unroll
        for (int mi = 0; mi < 2; mi++)
            #pragma unroll
            for (int j = 0; j < 8; j++) {
                acc[mi][j][0] = 0.f; acc[mi][j][1] = 0.f;
                acc[mi][j][2] = 0.f; acc[mi][j][3] = 0.f;
            }
        for (int ks = 0; ks < 9; ks++) {
            uint4 afA[NP], afB[NP];
            #pragma unroll
            for (int p = 0; p < NP; p++) {
                afA[p] = *(const uint4*)(XP + p*PLU + ((((2*wm  )*9 + ks)*32 + lane) << 2));
                afB[p] = *(const uint4*)(XP + p*PLU + ((((2*wm+1)*9 + ks)*32 + lane) << 2));
            }
            #pragma unroll
            for (int j = 0; j < 8; j++) {
                int nt = wn*8 + j;
                int boff = (((ks*16 + nt)*32 + lane) << 1);
                uint2 bfr[NP];
                #pragma unroll
                for (int p = 0; p < NP; p++)
                    bfr[p] = __ldg((const uint2*)(Wg + p*PLU + boff));
                #pragma unroll
                for (int q = 0; q < NPROD; q++) {
                    mma16816(acc[0][j], afA[PA[q]].x, afA[PA[q]].y, afA[PA[q]].z, afA[PA[q]].w,
                             bfr[PB[q]].x, bfr[PB[q]].y);
                    mma16816(acc[1][j], afB[PA[q]].x, afB[PA[q]].y, afB[PA[q]].z, afB[PA[q]].w,
                             bfr[PB[q]].x, bfr[PB[q]].y);
                }
            }
        }
        __syncthreads();

        #pragma unroll
        for (int mi = 0; mi < 2; mi++) {
            int mt = 2*wm + mi;
            #pragma unroll
            for (int j = 0; j < 8; j++) {
                int nt = wn*8 + j;
                int col = nt*8 + (tig << 1);
                float bA = bias_s[col], bB = bias_s[col + 1];
                float v0 = fmaxf(acc[mi][j][0] + bA, 0.f);
                float v1 = fmaxf(acc[mi][j][1] + bB, 0.f);
                float v2 = fmaxf(acc[mi][j][2] + bA, 0.f);
                float v3 = fmaxf(acc[mi][j][3] + bB, 0.f);
                int pi = nt*4 + tig;
                int adA = xf_addr(mt*16 + g, pi);
                float r0 = v0, r1 = v1, r2 = v2, r3 = v3;
                #pragma unroll
                for (int p = 0; p < NP; p++) {
                    u32 pkA = pack_bf16x2(r0, r1);
                    u32 pkB = pack_bf16x2(r2, r3);
                    *(uint2*)(XP + p*PLU + adA) = make_uint2(pkA, pkB);
                    r0 -= bf16lo_f(pkA); r1 -= bf16hi_f(pkA);
                    r2 -= bf16lo_f(pkB); r3 -= bf16hi_f(pkB);
                }
            }
        }
        __syncthreads();
    }

    // head: per-thread point (wph broadcast reads, L2/L1-hot)
    if (tid < 128) {
        float s0 = 0.f, s1 = 0.f, s2 = 0.f;
        #pragma unroll 8
        for (int kp = 0; kp < 64; kp++) {
            int ad = xf_addr(tid, kp);
            float x0 = 0.f, x1 = 0.f;
            #pragma unroll
            for (int p = 0; p < NP; p++) {
                u32 v = XP[p*PLU + ad];
                x0 += bf16lo_f(v); x1 += bf16hi_f(v);
            }
            int k = kp << 1;
            s0 += __ldg(&wph[k])*x0 + __ldg(&wph[k+1])*x1;
            s1 += __ldg(&wph[KIN + k])*x0 + __ldg(&wph[KIN + k + 1])*x1;
            s2 += __ldg(&wph[2*KIN + k])*x0 + __ldg(&wph[2*KIN + k + 1])*x1;
        }
        int id = g_idx[pBase + tid];
        sem[(size_t)(n*NCLS + 0)*HW + id] = hsum[tid] + s0;
        sem[(size_t)(n*NCLS + 1)*HW + id] = hsum[128 + tid] + s1;
        sem[(size_t)(n*NCLS + 2)*HW + id] = hsum[256 + tid] + s2;
    }
}

// ---------------- launch ----------------
extern "C" void kernel_launch(void* const* d_in, const int* in_sizes, int n_in,
                              void* d_out, int out_size) {
    const float* coarse = (const float*)d_in[0];
    const float* feat   = (const float*)d_in[1];
    const float* w1 = (const float*)d_in[2];
    const float* b1 = (const float*)d_in[3];
    const float* w2 = (const float*)d_in[4];
    const float* b2 = (const float*)d_in[5];
    const float* w3 = (const float*)d_in[6];
    const float* b3 = (const float*)d_in[7];
    const float* wp = (const float*)d_in[8];
    const float* bp = (const float*)d_in[9];
    float* out = (float*)d_out;

    float* sem256;
    cudaGetSymbolAddress((void**)&sem256, g_sem256);

    static cudaStream_t sSide = nullptr;
    static cudaEvent_t evFork = nullptr, evJoin = nullptr;
    if (sSide == nullptr) {
        cudaStreamCreateWithFlags(&sSide, cudaStreamNonBlocking);
        cudaEventCreateWithFlags(&evFork, cudaEventDisableTiming);
        cudaEventCreateWithFlags(&evJoin, cudaEventDisableTiming);
    }

    const int SM3 = 3*PLB + 2048;   // 112,640 B -> 2 blocks/SM
    const int SM2 = 2*PLB + 2048;   //  75,776 B -> 3 blocks/SM
    cudaFuncSetAttribute(mma_mlp<3>, cudaFuncAttributeMaxDynamicSharedMemorySize, SM3);
    cudaFuncSetAttribute(mma_mlp<2>, cudaFuncAttributeMaxDynamicSharedMemorySize, SM2);

    cudaEventRecord(evFork, 0);
    cudaStreamWaitEvent(sSide, evFork, 0);
    transpose_kernel<<<dim3(2048, 4, 4), dim3(32, 8), 0, sSide>>>(feat);
    cudaEventRecord(evJoin, sSide);

    prep_kernel<<<256, 256>>>(w1, w2, w3);

    for (int step = 0; step < 2; step++) {
        int logW = (step == 0) ? 8 : 9;
        int HW   = 1 << (2*logW);
        const float* semIn = (step == 0) ? coarse : sem256;
        float* semOut      = (step == 0) ? sem256 : out;

        upsample_sel<<<dim3(HW/1024, NB), 256>>>(semIn, semOut, logW);
        compact_sel<<<dim3(HW/4096, NB), 1024>>>(HW);

        if (step == 0) {
            cudaStreamWaitEvent(0, evJoin, 0);
            mma_mlp<3><<<PTOT/128, 256, SM3>>>(coarse, b1, b2, b3, wp, bp, semOut, HW, logW);
        } else {
            mma_mlp<2><<<PTOT/128, 256, SM2>>>(coarse, b1, b2, b3, wp, bp, semOut, HW, logW);
        }
    }
}